// round 1
// baseline (speedup 1.0000x reference)
#include <cuda_runtime.h>

// Problem constants
#define Bsz    2
#define Tseq   2048
#define Dmodel 2048
#define NHEAD  16
#define HD     128
#define FR     64      // rotary freqs = HD/2

// ---------------------------------------------------------------------------
// Scratch (static __device__ — no allocations allowed)
// Q,K,V in [B, N, T, H] layout; O in [B, T, D] layout.
// ---------------------------------------------------------------------------
__device__ float g_Q[(size_t)Bsz * NHEAD * Tseq * HD];
__device__ float g_K[(size_t)Bsz * NHEAD * Tseq * HD];
__device__ float g_V[(size_t)Bsz * NHEAD * Tseq * HD];
__device__ float g_O[(size_t)Bsz * Tseq * Dmodel];

// ---------------------------------------------------------------------------
// GEMM: C[M, NC] = A[M, 2048] * B[2048, NC]
//   MODE 0: A = x (param), epilogue scatters into g_Q / g_K / g_V ([B,N,T,H])
//   MODE 1: A = g_O,       epilogue writes C (d_out)
// Tiling: 128x128 block, BK=8, 256 threads, 8x8 per-thread micro-tile.
// All dims divide the tiles exactly (M=4096, NC in {6144,2048}, K=2048).
// ---------------------------------------------------------------------------
template <int MODE>
__global__ void __launch_bounds__(256) gemm_kernel(const float* __restrict__ A,
                                                   const float* __restrict__ Bm,
                                                   float* __restrict__ C,
                                                   int NC) {
    const int Kd = 2048;
    __shared__ float As[8][128];
    __shared__ float Bs[8][128];

    const int tid = threadIdx.x;
    const int m0 = blockIdx.y * 128;
    const int c0 = blockIdx.x * 128;

    const int arow = tid >> 1;           // 0..127
    const int acol = (tid & 1) << 2;     // 0 or 4
    const int brow = tid >> 5;           // 0..7
    const int bcol = (tid & 31) << 2;    // 0..124

    const int ty = tid >> 4;             // 0..15
    const int tx = tid & 15;             // 0..15

    const float* Aptr = (MODE == 1) ? g_O : A;

    float acc[8][8];
#pragma unroll
    for (int i = 0; i < 8; i++)
#pragma unroll
        for (int j = 0; j < 8; j++) acc[i][j] = 0.f;

    for (int k0 = 0; k0 < Kd; k0 += 8) {
        float4 av = *(const float4*)&Aptr[(size_t)(m0 + arow) * Kd + k0 + acol];
        As[acol + 0][arow] = av.x;
        As[acol + 1][arow] = av.y;
        As[acol + 2][arow] = av.z;
        As[acol + 3][arow] = av.w;
        *(float4*)&Bs[brow][bcol] =
            *(const float4*)&Bm[(size_t)(k0 + brow) * NC + c0 + bcol];
        __syncthreads();

#pragma unroll
        for (int kk = 0; kk < 8; kk++) {
            float a[8], b[8];
            *(float4*)&a[0] = *(const float4*)&As[kk][ty * 8];
            *(float4*)&a[4] = *(const float4*)&As[kk][ty * 8 + 4];
            *(float4*)&b[0] = *(const float4*)&Bs[kk][tx * 8];
            *(float4*)&b[4] = *(const float4*)&Bs[kk][tx * 8 + 4];
#pragma unroll
            for (int i = 0; i < 8; i++)
#pragma unroll
                for (int j = 0; j < 8; j++) acc[i][j] += a[i] * b[j];
        }
        __syncthreads();
    }

    if (MODE == 0) {
        // Column block is 128-aligned -> one (part, head) per block, h = tx*8+j
        const int part = c0 >> 11;           // 0=Q, 1=K, 2=V
        const int nh = (c0 >> 7) & 15;       // head
        float* dst = (part == 0) ? g_Q : (part == 1) ? g_K : g_V;
#pragma unroll
        for (int i = 0; i < 8; i++) {
            const int m = m0 + ty * 8 + i;
            const int bb = m >> 11;          // batch
            const int t = m & 2047;          // token
            float* rowp =
                &dst[((size_t)((bb << 4) + nh) * Tseq + t) * HD + tx * 8];
            *(float4*)&rowp[0] =
                make_float4(acc[i][0], acc[i][1], acc[i][2], acc[i][3]);
            *(float4*)&rowp[4] =
                make_float4(acc[i][4], acc[i][5], acc[i][6], acc[i][7]);
        }
    } else {
#pragma unroll
        for (int i = 0; i < 8; i++) {
            const int m = m0 + ty * 8 + i;
            float* rowp = &C[(size_t)m * NC + c0 + tx * 8];
            *(float4*)&rowp[0] =
                make_float4(acc[i][0], acc[i][1], acc[i][2], acc[i][3]);
            *(float4*)&rowp[4] =
                make_float4(acc[i][4], acc[i][5], acc[i][6], acc[i][7]);
        }
    }
}

// ---------------------------------------------------------------------------
// RoPE applied in-place to K and V (reference applies it to k AND v, not q).
// One thread per (b,n,t,f) pair.
// ---------------------------------------------------------------------------
__global__ void rope_kernel(const float* __restrict__ cosT,
                            const float* __restrict__ sinT) {
    const int idx = blockIdx.x * blockDim.x + threadIdx.x;
    if (idx >= Bsz * NHEAD * Tseq * FR) return;
    const int f = idx & 63;
    const int t = (idx >> 6) & 2047;
    const int bn = idx >> 17;                 // b*16+n  (T*F = 1<<17)
    const float c = cosT[t * FR + f];
    const float s = sinT[t * FR + f];
    const size_t base = ((size_t)bn * Tseq + t) * HD + (f << 1);

    float2 k = *(float2*)&g_K[base];
    *(float2*)&g_K[base] = make_float2(k.x * c - k.y * s, k.x * s + k.y * c);
    float2 v = *(float2*)&g_V[base];
    *(float2*)&g_V[base] = make_float2(v.x * c - v.y * s, v.x * s + v.y * c);
}

// ---------------------------------------------------------------------------
// Flash attention (causal), fp32.
// Grid: (qtile=T/128, head, batch). 256 threads.
// Thread pair (2*qi, 2*qi+1) owns query row qi; each half owns 64 head dims.
// Online softmax with per-16-key-tile rescale; causal loop truncation.
// ---------------------------------------------------------------------------
#define KT 16
__global__ void __launch_bounds__(256) attn_kernel() {
    __shared__ float Ks[KT][HD];
    __shared__ float Vs[KT][HD];

    const int b = blockIdx.z, n = blockIdx.y, qt = blockIdx.x;
    const int tid = threadIdx.x;
    const int qi = tid >> 1;
    const int half = tid & 1;
    const int q = qt * 128 + qi;
    const float scale = 0.08838834764831845f;  // 1/sqrt(128)

    const size_t headoff = (size_t)(b * NHEAD + n) * Tseq * HD;
    const float* Qp = &g_Q[headoff + (size_t)q * HD + half * 64];

    float qreg[64];
#pragma unroll
    for (int i = 0; i < 16; i++) {
        float4 v = *(const float4*)&Qp[i * 4];
        qreg[i * 4 + 0] = v.x * scale;
        qreg[i * 4 + 1] = v.y * scale;
        qreg[i * 4 + 2] = v.z * scale;
        qreg[i * 4 + 3] = v.w * scale;
    }

    float acc[64];
#pragma unroll
    for (int d = 0; d < 64; d++) acc[d] = 0.f;
    float m_i = -1e30f, l_i = 0.f;

    const float* Kb = &g_K[headoff];
    const float* Vb = &g_V[headoff];

    const int nkt = (qt + 1) * (128 / KT);  // causal: only tiles up to q block

    for (int kt = 0; kt < nkt; kt++) {
        const int j0 = kt * KT;
        __syncthreads();
#pragma unroll
        for (int r = 0; r < 2; r++) {
            const int e = tid + r * 256;        // 512 float4 per matrix
            const int row = e >> 5;
            const int col = (e & 31) << 2;
            *(float4*)&Ks[row][col] =
                *(const float4*)&Kb[(size_t)(j0 + row) * HD + col];
            *(float4*)&Vs[row][col] =
                *(const float4*)&Vb[(size_t)(j0 + row) * HD + col];
        }
        __syncthreads();

        float sreg[KT];
#pragma unroll
        for (int jj = 0; jj < KT; jj++) {
            const float* kr = &Ks[jj][half * 64];
            float s = 0.f;
#pragma unroll
            for (int d = 0; d < 64; d += 4) {
                float4 kv = *(const float4*)&kr[d];
                s += qreg[d] * kv.x + qreg[d + 1] * kv.y + qreg[d + 2] * kv.z +
                     qreg[d + 3] * kv.w;
            }
            s += __shfl_xor_sync(0xffffffffu, s, 1);
            sreg[jj] = (j0 + jj <= q) ? s : -1e30f;
        }

        float tmax = m_i;
#pragma unroll
        for (int jj = 0; jj < KT; jj++) tmax = fmaxf(tmax, sreg[jj]);
        const float corr = __expf(m_i - tmax);
        m_i = tmax;
        l_i *= corr;
#pragma unroll
        for (int d = 0; d < 64; d++) acc[d] *= corr;

#pragma unroll
        for (int jj = 0; jj < KT; jj++) {
            const float p = __expf(sreg[jj] - m_i);
            l_i += p;
            const float* vr = &Vs[jj][half * 64];
#pragma unroll
            for (int d = 0; d < 64; d += 4) {
                float4 vv = *(const float4*)&vr[d];
                acc[d] += p * vv.x;
                acc[d + 1] += p * vv.y;
                acc[d + 2] += p * vv.z;
                acc[d + 3] += p * vv.w;
            }
        }
    }

    const float inv = 1.f / l_i;
    // O in [B, T, D] layout for the out-projection GEMM
    float* Op = &g_O[((size_t)(b * Tseq + q)) * Dmodel + n * HD + half * 64];
#pragma unroll
    for (int i = 0; i < 16; i++) {
        *(float4*)&Op[i * 4] =
            make_float4(acc[i * 4] * inv, acc[i * 4 + 1] * inv,
                        acc[i * 4 + 2] * inv, acc[i * 4 + 3] * inv);
    }
}

// ---------------------------------------------------------------------------
// Host launcher (graph-capturable: launches only, default stream)
// Inputs: 0=x, 1=mask (unused: mask is exactly causal tril, handled by loop
// bounds), 2=cos, 3=sin, 4=w_attn, 5=w_out.
// ---------------------------------------------------------------------------
extern "C" void kernel_launch(void* const* d_in, const int* in_sizes, int n_in,
                              void* d_out, int out_size) {
    const float* x = (const float*)d_in[0];
    const float* cosT = (const float*)d_in[2];
    const float* sinT = (const float*)d_in[3];
    const float* w_attn = (const float*)d_in[4];
    const float* w_out = (const float*)d_in[5];
    float* out = (float*)d_out;

    // QKV projection: [4096,2048] x [2048,6144], scatter to Q/K/V [B,N,T,H]
    gemm_kernel<0><<<dim3(48, 32), 256>>>(x, w_attn, nullptr, 3 * Dmodel);

    // RoPE on K and V
    const int nrope = Bsz * NHEAD * Tseq * FR;
    rope_kernel<<<(nrope + 255) / 256, 256>>>(cosT, sinT);

    // Causal flash attention -> g_O [B,T,D]
    attn_kernel<<<dim3(Tseq / 128, NHEAD, Bsz), 256>>>();

    // Output projection: [4096,2048] x [2048,2048] -> d_out
    gemm_kernel<1><<<dim3(16, 32), 256>>>(nullptr, w_out, out, Dmodel);
}

// round 5
// speedup vs baseline: 1.5135x; 1.5135x over previous
#include <cuda_runtime.h>
#include <cuda_bf16.h>
#include <cstdint>

// Problem constants
#define Bsz    2
#define Tseq   2048
#define Dmodel 2048
#define NHEAD  16
#define HD     128
#define FR     64

// ---------------------------------------------------------------------------
// Scratch (static __device__ — no allocations allowed)
// ---------------------------------------------------------------------------
__device__ float g_Q[(size_t)Bsz * NHEAD * Tseq * HD];
__device__ float g_K[(size_t)Bsz * NHEAD * Tseq * HD];
__device__ float g_V[(size_t)Bsz * NHEAD * Tseq * HD];
__device__ float g_O[(size_t)Bsz * Tseq * Dmodel];

// split-bf16 operands
__device__ __nv_bfloat16 g_Xh[(size_t)Bsz * Tseq * Dmodel];
__device__ __nv_bfloat16 g_Xl[(size_t)Bsz * Tseq * Dmodel];
__device__ __nv_bfloat16 g_Wh[(size_t)3 * Dmodel * Dmodel];   // w_attn^T [6144][2048]
__device__ __nv_bfloat16 g_Wl[(size_t)3 * Dmodel * Dmodel];
__device__ __nv_bfloat16 g_WOh[(size_t)Dmodel * Dmodel];      // w_out^T [2048][2048]
__device__ __nv_bfloat16 g_WOl[(size_t)Dmodel * Dmodel];
__device__ __nv_bfloat16 g_Oh[(size_t)Bsz * Tseq * Dmodel];
__device__ __nv_bfloat16 g_Ol[(size_t)Bsz * Tseq * Dmodel];

// ---------------------------------------------------------------------------
// mma.sync / ldmatrix / cp.async helpers (sm_80+ baseline PTX)
// ---------------------------------------------------------------------------
__device__ __forceinline__ uint32_t smem_u32(const void* p) {
    uint32_t a;
    asm("{ .reg .u64 t; cvta.to.shared.u64 t, %1; cvt.u32.u64 %0, t; }"
        : "=r"(a) : "l"(p));
    return a;
}

#define LDSM4(r, addr) \
    asm volatile("ldmatrix.sync.aligned.m8n8.x4.shared.b16 {%0,%1,%2,%3}, [%4];" \
                 : "=r"((r)[0]), "=r"((r)[1]), "=r"((r)[2]), "=r"((r)[3]) \
                 : "r"(addr))

__device__ __forceinline__ void mma_16816(float* c, const uint32_t* a,
                                          const uint32_t* b) {
    asm volatile(
        "mma.sync.aligned.m16n8k16.row.col.f32.bf16.bf16.f32 "
        "{%0,%1,%2,%3}, {%4,%5,%6,%7}, {%8,%9}, {%0,%1,%2,%3};"
        : "+f"(c[0]), "+f"(c[1]), "+f"(c[2]), "+f"(c[3])
        : "r"(a[0]), "r"(a[1]), "r"(a[2]), "r"(a[3]), "r"(b[0]), "r"(b[1]));
}

#define CP16(dst, src) \
    asm volatile("cp.async.cg.shared.global [%0], [%1], 16;" \
                 :: "r"(dst), "l"(src) : "memory")
#define CP_COMMIT() asm volatile("cp.async.commit_group;" ::: "memory")
#define CP_WAIT1()  asm volatile("cp.async.wait_group 1;" ::: "memory")
#define CP_WAIT0()  asm volatile("cp.async.wait_group 0;" ::: "memory")

// ---------------------------------------------------------------------------
// fp32 -> (bf16 hi, bf16 lo) elementwise split
// ---------------------------------------------------------------------------
__global__ void convert_split(const float* __restrict__ in,
                              __nv_bfloat16* __restrict__ hi,
                              __nv_bfloat16* __restrict__ lo, int n4) {
    const int i = blockIdx.x * blockDim.x + threadIdx.x;
    if (i >= n4) return;
    float4 a = ((const float4*)in)[i];
    __nv_bfloat16 h0 = __float2bfloat16(a.x);
    __nv_bfloat16 h1 = __float2bfloat16(a.y);
    __nv_bfloat16 h2 = __float2bfloat16(a.z);
    __nv_bfloat16 h3 = __float2bfloat16(a.w);
    __nv_bfloat16 l0 = __float2bfloat16(a.x - __bfloat162float(h0));
    __nv_bfloat16 l1 = __float2bfloat16(a.y - __bfloat162float(h1));
    __nv_bfloat16 l2 = __float2bfloat16(a.z - __bfloat162float(h2));
    __nv_bfloat16 l3 = __float2bfloat16(a.w - __bfloat162float(h3));
    ((__nv_bfloat162*)hi)[i * 2 + 0] = __halves2bfloat162(h0, h1);
    ((__nv_bfloat162*)hi)[i * 2 + 1] = __halves2bfloat162(h2, h3);
    ((__nv_bfloat162*)lo)[i * 2 + 0] = __halves2bfloat162(l0, l1);
    ((__nv_bfloat162*)lo)[i * 2 + 1] = __halves2bfloat162(l2, l3);
}

// ---------------------------------------------------------------------------
// Transpose W [K, Ncols] (row-major) -> Wt [Ncols, K] with hi/lo bf16 split
// ---------------------------------------------------------------------------
__global__ void convert_wT(const float* __restrict__ W,
                           __nv_bfloat16* __restrict__ Th,
                           __nv_bfloat16* __restrict__ Tl, int K, int Ncols) {
    __shared__ float s[32][33];
    const int n0 = blockIdx.x * 32, k0 = blockIdx.y * 32;
    const int tx = threadIdx.x, ty = threadIdx.y;  // (32, 8)
#pragma unroll
    for (int i = 0; i < 4; i++)
        s[ty + i * 8][tx] = W[(size_t)(k0 + ty + i * 8) * Ncols + n0 + tx];
    __syncthreads();
#pragma unroll
    for (int i = 0; i < 4; i++) {
        const float a = s[tx][ty + i * 8];
        const __nv_bfloat16 h = __float2bfloat16(a);
        const __nv_bfloat16 l = __float2bfloat16(a - __bfloat162float(h));
        const size_t o = (size_t)(n0 + ty + i * 8) * K + k0 + tx;
        Th[o] = h;
        Tl[o] = l;
    }
}

// ---------------------------------------------------------------------------
// mma.sync split-bf16 GEMM: C[M,NC] = A[M,2048] * B^T (B stored [NC,2048])
// CTA tile 128x128, K-chunk 32, 8 warps (warp tile 64x32), double-buffered
// cp.async. Splits: acc = Ah*Bh + Al*Bh + Ah*Bl.
// ---------------------------------------------------------------------------
#define RSTRIDE 40                      // bf16 elems per smem row (32 data + 8 pad)
#define TILE_B  (128 * RSTRIDE * 2)     // 10240 bytes per tile
#define STAGE_B (4 * TILE_B)            // 40960 bytes per stage
#define GSMEM_BYTES (2 * STAGE_B)       // 81920

template <int MODE>
__global__ void __launch_bounds__(256) gemm_tc(
    const __nv_bfloat16* __restrict__ Ah, const __nv_bfloat16* __restrict__ Al,
    const __nv_bfloat16* __restrict__ Bh, const __nv_bfloat16* __restrict__ Bl,
    float* __restrict__ C) {
    extern __shared__ char smem[];
    const uint32_t sb = smem_u32(smem);

    const int tid = threadIdx.x;
    const int lane = tid & 31, warp = tid >> 5;
    const int m0 = blockIdx.y * 128, c0 = blockIdx.x * 128;
    const int wm = (warp & 1) * 64, wn = (warp >> 1) * 32;

    // ldmatrix lane addressing
    const int a_row = wm + (lane & 15);
    const int a_colb = (lane >> 4) * 16;
    const int b_row = wn + (lane & 7) + ((lane >> 4) << 3);
    const int b_colb = ((lane >> 3) & 1) * 16;

    // Base pointers for this CTA's row blocks
    const __nv_bfloat16* Ah0 = Ah + (size_t)m0 * 2048;
    const __nv_bfloat16* Al0 = Al + (size_t)m0 * 2048;
    const __nv_bfloat16* Bh0 = Bh + (size_t)c0 * 2048;
    const __nv_bfloat16* Bl0 = Bl + (size_t)c0 * 2048;

    float acc[4][4][4];
#pragma unroll
    for (int i = 0; i < 4; i++)
#pragma unroll
        for (int j = 0; j < 4; j++)
#pragma unroll
            for (int r = 0; r < 4; r++) acc[i][j][r] = 0.f;

    // Stage loader: full tile = 128 rows x 64 bytes = 512 x 16B chunks per
    // matrix; each of 256 threads loads chunks tid and tid+256. (R3 bug: only
    // half the tile was loaded -> uninitialized smem -> NaN.)
    auto load_stage = [&](int stage, int kc) {
        const uint32_t s0 = sb + stage * STAGE_B;
        const size_t ko = (size_t)kc * 32;
#pragma unroll
        for (int h = 0; h < 2; h++) {
            const int cch = tid + h * 256;          // 0..511
            const int row = cch >> 2, q = cch & 3;  // row 0..127, 16B quarter
            const uint32_t so = (uint32_t)row * (RSTRIDE * 2) + q * 16;
            const size_t go = (size_t)row * 2048 + ko + q * 8;
            CP16(s0 + 0 * TILE_B + so, Ah0 + go);
            CP16(s0 + 1 * TILE_B + so, Al0 + go);
            CP16(s0 + 2 * TILE_B + so, Bh0 + go);
            CP16(s0 + 3 * TILE_B + so, Bl0 + go);
        }
        CP_COMMIT();
    };

    load_stage(0, 0);

    for (int c = 0; c < 64; c++) {
        if (c < 63) {
            load_stage((c + 1) & 1, c + 1);
            CP_WAIT1();
        } else {
            CP_WAIT0();
        }
        __syncthreads();

        const uint32_t st = sb + (c & 1) * STAGE_B;
        const uint32_t tAh = st + 0 * TILE_B, tAl = st + 1 * TILE_B;
        const uint32_t tBh = st + 2 * TILE_B, tBl = st + 3 * TILE_B;

#pragma unroll
        for (int t = 0; t < 2; t++) {
            const int tcb = t * 32;
            uint32_t aF[4][4], bF[4][2];

            // pass 1: Ah * Bh
#pragma unroll
            for (int mf = 0; mf < 4; mf++)
                LDSM4(aF[mf], tAh + (a_row + mf * 16) * (RSTRIDE * 2) + tcb + a_colb);
#pragma unroll
            for (int nf2 = 0; nf2 < 2; nf2++) {
                uint32_t r[4];
                LDSM4(r, tBh + (b_row + nf2 * 16) * (RSTRIDE * 2) + tcb + b_colb);
                bF[nf2 * 2][0] = r[0]; bF[nf2 * 2][1] = r[1];
                bF[nf2 * 2 + 1][0] = r[2]; bF[nf2 * 2 + 1][1] = r[3];
            }
#pragma unroll
            for (int mf = 0; mf < 4; mf++)
#pragma unroll
                for (int nf = 0; nf < 4; nf++) mma_16816(acc[mf][nf], aF[mf], bF[nf]);

            // pass 2: Al * Bh  (reuse bF)
#pragma unroll
            for (int mf = 0; mf < 4; mf++)
                LDSM4(aF[mf], tAl + (a_row + mf * 16) * (RSTRIDE * 2) + tcb + a_colb);
#pragma unroll
            for (int mf = 0; mf < 4; mf++)
#pragma unroll
                for (int nf = 0; nf < 4; nf++) mma_16816(acc[mf][nf], aF[mf], bF[nf]);

            // pass 3: Ah * Bl  (reload Ah, load Bl)
#pragma unroll
            for (int mf = 0; mf < 4; mf++)
                LDSM4(aF[mf], tAh + (a_row + mf * 16) * (RSTRIDE * 2) + tcb + a_colb);
#pragma unroll
            for (int nf2 = 0; nf2 < 2; nf2++) {
                uint32_t r[4];
                LDSM4(r, tBl + (b_row + nf2 * 16) * (RSTRIDE * 2) + tcb + b_colb);
                bF[nf2 * 2][0] = r[0]; bF[nf2 * 2][1] = r[1];
                bF[nf2 * 2 + 1][0] = r[2]; bF[nf2 * 2 + 1][1] = r[3];
            }
#pragma unroll
            for (int mf = 0; mf < 4; mf++)
#pragma unroll
                for (int nf = 0; nf < 4; nf++) mma_16816(acc[mf][nf], aF[mf], bF[nf]);
        }
        __syncthreads();
    }

    // Epilogue
    const int g = lane >> 2, tg = lane & 3;
#pragma unroll
    for (int mf = 0; mf < 4; mf++) {
#pragma unroll
        for (int nf = 0; nf < 4; nf++) {
            const int row0 = m0 + wm + mf * 16 + g;
            const int col = c0 + wn + nf * 8 + tg * 2;
            if (MODE == 0) {
                const int part = col >> 11;
                const int nh = (col >> 7) & 15;
                const int h = col & 127;
                float* base = (part == 0) ? g_Q : (part == 1) ? g_K : g_V;
#pragma unroll
                for (int rr = 0; rr < 2; rr++) {
                    const int row = row0 + rr * 8;
                    const int bb = row >> 11, tt = row & 2047;
                    float2* dp = (float2*)&base[((size_t)((bb << 4) + nh) * Tseq + tt) * HD + h];
                    *dp = make_float2(acc[mf][nf][rr * 2], acc[mf][nf][rr * 2 + 1]);
                }
            } else {
#pragma unroll
                for (int rr = 0; rr < 2; rr++) {
                    const int row = row0 + rr * 8;
                    float2* dp = (float2*)&C[(size_t)row * 2048 + col];
                    *dp = make_float2(acc[mf][nf][rr * 2], acc[mf][nf][rr * 2 + 1]);
                }
            }
        }
    }
}

// ---------------------------------------------------------------------------
// RoPE applied in-place to K and V
// ---------------------------------------------------------------------------
__global__ void rope_kernel(const float* __restrict__ cosT,
                            const float* __restrict__ sinT) {
    const int idx = blockIdx.x * blockDim.x + threadIdx.x;
    if (idx >= Bsz * NHEAD * Tseq * FR) return;
    const int f = idx & 63;
    const int t = (idx >> 6) & 2047;
    const int bn = idx >> 17;
    const float c = cosT[t * FR + f];
    const float s = sinT[t * FR + f];
    const size_t base = ((size_t)bn * Tseq + t) * HD + (f << 1);

    float2 k = *(float2*)&g_K[base];
    *(float2*)&g_K[base] = make_float2(k.x * c - k.y * s, k.x * s + k.y * c);
    float2 v = *(float2*)&g_V[base];
    *(float2*)&g_V[base] = make_float2(v.x * c - v.y * s, v.x * s + v.y * c);
}

// ---------------------------------------------------------------------------
// Flash attention (causal), fp32 — unchanged from R1-passing kernel
// ---------------------------------------------------------------------------
#define KT 16
__global__ void __launch_bounds__(256) attn_kernel() {
    __shared__ float Ks[KT][HD];
    __shared__ float Vs[KT][HD];

    const int b = blockIdx.z, n = blockIdx.y, qt = blockIdx.x;
    const int tid = threadIdx.x;
    const int qi = tid >> 1;
    const int half = tid & 1;
    const int q = qt * 128 + qi;
    const float scale = 0.08838834764831845f;

    const size_t headoff = (size_t)(b * NHEAD + n) * Tseq * HD;
    const float* Qp = &g_Q[headoff + (size_t)q * HD + half * 64];

    float qreg[64];
#pragma unroll
    for (int i = 0; i < 16; i++) {
        float4 v = *(const float4*)&Qp[i * 4];
        qreg[i * 4 + 0] = v.x * scale;
        qreg[i * 4 + 1] = v.y * scale;
        qreg[i * 4 + 2] = v.z * scale;
        qreg[i * 4 + 3] = v.w * scale;
    }

    float acc[64];
#pragma unroll
    for (int d = 0; d < 64; d++) acc[d] = 0.f;
    float m_i = -1e30f, l_i = 0.f;

    const float* Kb = &g_K[headoff];
    const float* Vb = &g_V[headoff];

    const int nkt = (qt + 1) * (128 / KT);

    for (int kt = 0; kt < nkt; kt++) {
        const int j0 = kt * KT;
        __syncthreads();
#pragma unroll
        for (int r = 0; r < 2; r++) {
            const int e = tid + r * 256;
            const int row = e >> 5;
            const int col = (e & 31) << 2;
            *(float4*)&Ks[row][col] =
                *(const float4*)&Kb[(size_t)(j0 + row) * HD + col];
            *(float4*)&Vs[row][col] =
                *(const float4*)&Vb[(size_t)(j0 + row) * HD + col];
        }
        __syncthreads();

        float sreg[KT];
#pragma unroll
        for (int jj = 0; jj < KT; jj++) {
            const float* kr = &Ks[jj][half * 64];
            float s = 0.f;
#pragma unroll
            for (int d = 0; d < 64; d += 4) {
                float4 kv = *(const float4*)&kr[d];
                s += qreg[d] * kv.x + qreg[d + 1] * kv.y + qreg[d + 2] * kv.z +
                     qreg[d + 3] * kv.w;
            }
            s += __shfl_xor_sync(0xffffffffu, s, 1);
            sreg[jj] = (j0 + jj <= q) ? s : -1e30f;
        }

        float tmax = m_i;
#pragma unroll
        for (int jj = 0; jj < KT; jj++) tmax = fmaxf(tmax, sreg[jj]);
        const float corr = __expf(m_i - tmax);
        m_i = tmax;
        l_i *= corr;
#pragma unroll
        for (int d = 0; d < 64; d++) acc[d] *= corr;

#pragma unroll
        for (int jj = 0; jj < KT; jj++) {
            const float p = __expf(sreg[jj] - m_i);
            l_i += p;
            const float* vr = &Vs[jj][half * 64];
#pragma unroll
            for (int d = 0; d < 64; d += 4) {
                float4 vv = *(const float4*)&vr[d];
                acc[d] += p * vv.x;
                acc[d + 1] += p * vv.y;
                acc[d + 2] += p * vv.z;
                acc[d + 3] += p * vv.w;
            }
        }
    }

    const float inv = 1.f / l_i;
    float* Op = &g_O[((size_t)(b * Tseq + q)) * Dmodel + n * HD + half * 64];
#pragma unroll
    for (int i = 0; i < 16; i++) {
        *(float4*)&Op[i * 4] =
            make_float4(acc[i * 4] * inv, acc[i * 4 + 1] * inv,
                        acc[i * 4 + 2] * inv, acc[i * 4 + 3] * inv);
    }
}

// ---------------------------------------------------------------------------
// Host launcher (graph-capturable: kernel launches only)
// Inputs: 0=x, 1=mask(unused: exact causal tril), 2=cos, 3=sin, 4=w_attn, 5=w_out
// ---------------------------------------------------------------------------
extern "C" void kernel_launch(void* const* d_in, const int* in_sizes, int n_in,
                              void* d_out, int out_size) {
    const float* x = (const float*)d_in[0];
    const float* cosT = (const float*)d_in[2];
    const float* sinT = (const float*)d_in[3];
    const float* w_attn = (const float*)d_in[4];
    const float* w_out = (const float*)d_in[5];
    float* out = (float*)d_out;

    cudaFuncSetAttribute(gemm_tc<0>, cudaFuncAttributeMaxDynamicSharedMemorySize,
                         GSMEM_BYTES);
    cudaFuncSetAttribute(gemm_tc<1>, cudaFuncAttributeMaxDynamicSharedMemorySize,
                         GSMEM_BYTES);

    __nv_bfloat16 *pXh, *pXl, *pWh, *pWl, *pWOh, *pWOl, *pOh, *pOl;
    cudaGetSymbolAddress((void**)&pXh, g_Xh);
    cudaGetSymbolAddress((void**)&pXl, g_Xl);
    cudaGetSymbolAddress((void**)&pWh, g_Wh);
    cudaGetSymbolAddress((void**)&pWl, g_Wl);
    cudaGetSymbolAddress((void**)&pWOh, g_WOh);
    cudaGetSymbolAddress((void**)&pWOl, g_WOl);
    cudaGetSymbolAddress((void**)&pOh, g_Oh);
    cudaGetSymbolAddress((void**)&pOl, g_Ol);
    float* pOf;
    cudaGetSymbolAddress((void**)&pOf, g_O);

    // Operand preparation
    const int n4x = (Bsz * Tseq * Dmodel) / 4;
    convert_split<<<n4x / 256, 256>>>(x, pXh, pXl, n4x);
    convert_wT<<<dim3(3 * Dmodel / 32, Dmodel / 32), dim3(32, 8)>>>(
        w_attn, pWh, pWl, Dmodel, 3 * Dmodel);
    convert_wT<<<dim3(Dmodel / 32, Dmodel / 32), dim3(32, 8)>>>(
        w_out, pWOh, pWOl, Dmodel, Dmodel);

    // QKV projection (mma.sync split-bf16), scatter to Q/K/V [B,N,T,H]
    gemm_tc<0><<<dim3(48, 32), 256, GSMEM_BYTES>>>(pXh, pXl, pWh, pWl, nullptr);

    // RoPE on K and V
    const int nrope = Bsz * NHEAD * Tseq * FR;
    rope_kernel<<<(nrope + 255) / 256, 256>>>(cosT, sinT);

    // Causal flash attention -> g_O [B,T,D]
    attn_kernel<<<dim3(Tseq / 128, NHEAD, Bsz), 256>>>();

    // Split attention output, then output projection -> d_out
    convert_split<<<n4x / 256, 256>>>(pOf, pOh, pOl, n4x);
    gemm_tc<1><<<dim3(16, 32), 256, GSMEM_BYTES>>>(pOh, pOl, pWOh, pWOl, out);
}

// round 6
// speedup vs baseline: 3.5736x; 2.3612x over previous
#include <cuda_runtime.h>
#include <cuda_bf16.h>
#include <cstdint>

// Problem constants
#define Bsz    2
#define Tseq   2048
#define Dmodel 2048
#define NHEAD  16
#define HD     128
#define FR     64

// ---------------------------------------------------------------------------
// Scratch (static __device__ — no allocations allowed)
// ---------------------------------------------------------------------------
// split-bf16 operands for the projections
__device__ __nv_bfloat16 g_Xh[(size_t)Bsz * Tseq * Dmodel];
__device__ __nv_bfloat16 g_Xl[(size_t)Bsz * Tseq * Dmodel];
__device__ __nv_bfloat16 g_Wh[(size_t)3 * Dmodel * Dmodel];   // w_attn^T [6144][2048]
__device__ __nv_bfloat16 g_Wl[(size_t)3 * Dmodel * Dmodel];
__device__ __nv_bfloat16 g_WOh[(size_t)Dmodel * Dmodel];      // w_out^T [2048][2048]
__device__ __nv_bfloat16 g_WOl[(size_t)Dmodel * Dmodel];
// split-bf16 Q/K/V in [B,N,T,H] (Q pre-scaled, K/V post-rope)
__device__ __nv_bfloat16 g_Qh[(size_t)Bsz * NHEAD * Tseq * HD];
__device__ __nv_bfloat16 g_Ql[(size_t)Bsz * NHEAD * Tseq * HD];
__device__ __nv_bfloat16 g_Kh2[(size_t)Bsz * NHEAD * Tseq * HD];
__device__ __nv_bfloat16 g_Kl2[(size_t)Bsz * NHEAD * Tseq * HD];
__device__ __nv_bfloat16 g_Vh2[(size_t)Bsz * NHEAD * Tseq * HD];
__device__ __nv_bfloat16 g_Vl2[(size_t)Bsz * NHEAD * Tseq * HD];
// split-bf16 attention output [B,T,D]
__device__ __nv_bfloat16 g_Oh[(size_t)Bsz * Tseq * Dmodel];
__device__ __nv_bfloat16 g_Ol[(size_t)Bsz * Tseq * Dmodel];

// ---------------------------------------------------------------------------
// mma.sync / ldmatrix / cp.async helpers (sm_80+ baseline PTX)
// ---------------------------------------------------------------------------
__device__ __forceinline__ uint32_t smem_u32(const void* p) {
    uint32_t a;
    asm("{ .reg .u64 t; cvta.to.shared.u64 t, %1; cvt.u32.u64 %0, t; }"
        : "=r"(a) : "l"(p));
    return a;
}

#define LDSM4(r, addr) \
    asm volatile("ldmatrix.sync.aligned.m8n8.x4.shared.b16 {%0,%1,%2,%3}, [%4];" \
                 : "=r"((r)[0]), "=r"((r)[1]), "=r"((r)[2]), "=r"((r)[3]) \
                 : "r"(addr))
#define LDSM4T(r, addr) \
    asm volatile("ldmatrix.sync.aligned.m8n8.x4.trans.shared.b16 {%0,%1,%2,%3}, [%4];" \
                 : "=r"((r)[0]), "=r"((r)[1]), "=r"((r)[2]), "=r"((r)[3]) \
                 : "r"(addr))

__device__ __forceinline__ void mma_16816(float* c, const uint32_t* a,
                                          const uint32_t* b) {
    asm volatile(
        "mma.sync.aligned.m16n8k16.row.col.f32.bf16.bf16.f32 "
        "{%0,%1,%2,%3}, {%4,%5,%6,%7}, {%8,%9}, {%0,%1,%2,%3};"
        : "+f"(c[0]), "+f"(c[1]), "+f"(c[2]), "+f"(c[3])
        : "r"(a[0]), "r"(a[1]), "r"(a[2]), "r"(a[3]), "r"(b[0]), "r"(b[1]));
}

#define CP16(dst, src) \
    asm volatile("cp.async.cg.shared.global [%0], [%1], 16;" \
                 :: "r"(dst), "l"(src) : "memory")
#define CP_COMMIT() asm volatile("cp.async.commit_group;" ::: "memory")
#define CP_WAIT1()  asm volatile("cp.async.wait_group 1;" ::: "memory")
#define CP_WAIT0()  asm volatile("cp.async.wait_group 0;" ::: "memory")

__device__ __forceinline__ uint32_t pack_bf16x2(float x, float y) {
    __nv_bfloat162 h = __halves2bfloat162(__float2bfloat16(x), __float2bfloat16(y));
    return *(uint32_t*)&h;
}
__device__ __forceinline__ void split_store(__nv_bfloat16* hi, __nv_bfloat16* lo,
                                            size_t idx, float v0, float v1) {
    __nv_bfloat16 h0 = __float2bfloat16(v0);
    __nv_bfloat16 h1 = __float2bfloat16(v1);
    __nv_bfloat16 l0 = __float2bfloat16(v0 - __bfloat162float(h0));
    __nv_bfloat16 l1 = __float2bfloat16(v1 - __bfloat162float(h1));
    *(__nv_bfloat162*)&hi[idx] = __halves2bfloat162(h0, h1);
    *(__nv_bfloat162*)&lo[idx] = __halves2bfloat162(l0, l1);
}

// ---------------------------------------------------------------------------
// fp32 -> (bf16 hi, bf16 lo) elementwise split
// ---------------------------------------------------------------------------
__global__ void convert_split(const float* __restrict__ in,
                              __nv_bfloat16* __restrict__ hi,
                              __nv_bfloat16* __restrict__ lo, int n4) {
    const int i = blockIdx.x * blockDim.x + threadIdx.x;
    if (i >= n4) return;
    float4 a = ((const float4*)in)[i];
    __nv_bfloat16 h0 = __float2bfloat16(a.x);
    __nv_bfloat16 h1 = __float2bfloat16(a.y);
    __nv_bfloat16 h2 = __float2bfloat16(a.z);
    __nv_bfloat16 h3 = __float2bfloat16(a.w);
    __nv_bfloat16 l0 = __float2bfloat16(a.x - __bfloat162float(h0));
    __nv_bfloat16 l1 = __float2bfloat16(a.y - __bfloat162float(h1));
    __nv_bfloat16 l2 = __float2bfloat16(a.z - __bfloat162float(h2));
    __nv_bfloat16 l3 = __float2bfloat16(a.w - __bfloat162float(h3));
    ((__nv_bfloat162*)hi)[i * 2 + 0] = __halves2bfloat162(h0, h1);
    ((__nv_bfloat162*)hi)[i * 2 + 1] = __halves2bfloat162(h2, h3);
    ((__nv_bfloat162*)lo)[i * 2 + 0] = __halves2bfloat162(l0, l1);
    ((__nv_bfloat162*)lo)[i * 2 + 1] = __halves2bfloat162(l2, l3);
}

// ---------------------------------------------------------------------------
// Transpose W [K, Ncols] (row-major) -> Wt [Ncols, K] with hi/lo bf16 split
// ---------------------------------------------------------------------------
__global__ void convert_wT(const float* __restrict__ W,
                           __nv_bfloat16* __restrict__ Th,
                           __nv_bfloat16* __restrict__ Tl, int K, int Ncols) {
    __shared__ float s[32][33];
    const int n0 = blockIdx.x * 32, k0 = blockIdx.y * 32;
    const int tx = threadIdx.x, ty = threadIdx.y;  // (32, 8)
#pragma unroll
    for (int i = 0; i < 4; i++)
        s[ty + i * 8][tx] = W[(size_t)(k0 + ty + i * 8) * Ncols + n0 + tx];
    __syncthreads();
#pragma unroll
    for (int i = 0; i < 4; i++) {
        const float a = s[tx][ty + i * 8];
        const __nv_bfloat16 h = __float2bfloat16(a);
        const __nv_bfloat16 l = __float2bfloat16(a - __bfloat162float(h));
        const size_t o = (size_t)(n0 + ty + i * 8) * K + k0 + tx;
        Th[o] = h;
        Tl[o] = l;
    }
}

// ---------------------------------------------------------------------------
// mma.sync split-bf16 GEMM. MODE 0: QKV proj with fused scale(Q)/rope(K,V)
// and split-bf16 scatter to [B,N,T,H]. MODE 1: out-proj -> d_out (fp32).
// ---------------------------------------------------------------------------
#define RSTRIDE 40
#define TILE_B  (128 * RSTRIDE * 2)
#define STAGE_B (4 * TILE_B)
#define GSMEM_BYTES (2 * STAGE_B)

template <int MODE>
__global__ void __launch_bounds__(256) gemm_tc(
    const __nv_bfloat16* __restrict__ Ah, const __nv_bfloat16* __restrict__ Al,
    const __nv_bfloat16* __restrict__ Bh, const __nv_bfloat16* __restrict__ Bl,
    float* __restrict__ C,
    const float* __restrict__ cosT, const float* __restrict__ sinT) {
    extern __shared__ char smem[];
    const uint32_t sb = smem_u32(smem);

    const int tid = threadIdx.x;
    const int lane = tid & 31, warp = tid >> 5;
    const int m0 = blockIdx.y * 128, c0 = blockIdx.x * 128;
    const int wm = (warp & 1) * 64, wn = (warp >> 1) * 32;

    const int a_row = wm + (lane & 15);
    const int a_colb = (lane >> 4) * 16;
    const int b_row = wn + (lane & 7) + ((lane >> 4) << 3);
    const int b_colb = ((lane >> 3) & 1) * 16;

    const __nv_bfloat16* Ah0 = Ah + (size_t)m0 * 2048;
    const __nv_bfloat16* Al0 = Al + (size_t)m0 * 2048;
    const __nv_bfloat16* Bh0 = Bh + (size_t)c0 * 2048;
    const __nv_bfloat16* Bl0 = Bl + (size_t)c0 * 2048;

    float acc[4][4][4];
#pragma unroll
    for (int i = 0; i < 4; i++)
#pragma unroll
        for (int j = 0; j < 4; j++)
#pragma unroll
            for (int r = 0; r < 4; r++) acc[i][j][r] = 0.f;

    auto load_stage = [&](int stage, int kc) {
        const uint32_t s0 = sb + stage * STAGE_B;
        const size_t ko = (size_t)kc * 32;
#pragma unroll
        for (int h = 0; h < 2; h++) {
            const int cch = tid + h * 256;
            const int row = cch >> 2, q = cch & 3;
            const uint32_t so = (uint32_t)row * (RSTRIDE * 2) + q * 16;
            const size_t go = (size_t)row * 2048 + ko + q * 8;
            CP16(s0 + 0 * TILE_B + so, Ah0 + go);
            CP16(s0 + 1 * TILE_B + so, Al0 + go);
            CP16(s0 + 2 * TILE_B + so, Bh0 + go);
            CP16(s0 + 3 * TILE_B + so, Bl0 + go);
        }
        CP_COMMIT();
    };

    load_stage(0, 0);

    for (int c = 0; c < 64; c++) {
        if (c < 63) {
            load_stage((c + 1) & 1, c + 1);
            CP_WAIT1();
        } else {
            CP_WAIT0();
        }
        __syncthreads();

        const uint32_t st = sb + (c & 1) * STAGE_B;
        const uint32_t tAh = st + 0 * TILE_B, tAl = st + 1 * TILE_B;
        const uint32_t tBh = st + 2 * TILE_B, tBl = st + 3 * TILE_B;

#pragma unroll
        for (int t = 0; t < 2; t++) {
            const int tcb = t * 32;
            uint32_t aF[4][4], bF[4][2];

#pragma unroll
            for (int mf = 0; mf < 4; mf++)
                LDSM4(aF[mf], tAh + (a_row + mf * 16) * (RSTRIDE * 2) + tcb + a_colb);
#pragma unroll
            for (int nf2 = 0; nf2 < 2; nf2++) {
                uint32_t r[4];
                LDSM4(r, tBh + (b_row + nf2 * 16) * (RSTRIDE * 2) + tcb + b_colb);
                bF[nf2 * 2][0] = r[0]; bF[nf2 * 2][1] = r[1];
                bF[nf2 * 2 + 1][0] = r[2]; bF[nf2 * 2 + 1][1] = r[3];
            }
#pragma unroll
            for (int mf = 0; mf < 4; mf++)
#pragma unroll
                for (int nf = 0; nf < 4; nf++) mma_16816(acc[mf][nf], aF[mf], bF[nf]);

#pragma unroll
            for (int mf = 0; mf < 4; mf++)
                LDSM4(aF[mf], tAl + (a_row + mf * 16) * (RSTRIDE * 2) + tcb + a_colb);
#pragma unroll
            for (int mf = 0; mf < 4; mf++)
#pragma unroll
                for (int nf = 0; nf < 4; nf++) mma_16816(acc[mf][nf], aF[mf], bF[nf]);

#pragma unroll
            for (int mf = 0; mf < 4; mf++)
                LDSM4(aF[mf], tAh + (a_row + mf * 16) * (RSTRIDE * 2) + tcb + a_colb);
#pragma unroll
            for (int nf2 = 0; nf2 < 2; nf2++) {
                uint32_t r[4];
                LDSM4(r, tBl + (b_row + nf2 * 16) * (RSTRIDE * 2) + tcb + b_colb);
                bF[nf2 * 2][0] = r[0]; bF[nf2 * 2][1] = r[1];
                bF[nf2 * 2 + 1][0] = r[2]; bF[nf2 * 2 + 1][1] = r[3];
            }
#pragma unroll
            for (int mf = 0; mf < 4; mf++)
#pragma unroll
                for (int nf = 0; nf < 4; nf++) mma_16816(acc[mf][nf], aF[mf], bF[nf]);
        }
        __syncthreads();
    }

    // Epilogue
    const int g = lane >> 2, tg = lane & 3;
#pragma unroll
    for (int mf = 0; mf < 4; mf++) {
#pragma unroll
        for (int nf = 0; nf < 4; nf++) {
            const int row0 = m0 + wm + mf * 16 + g;
            const int col = c0 + wn + nf * 8 + tg * 2;  // even
            if (MODE == 0) {
                const int part = col >> 11;           // 0=Q,1=K,2=V
                const int nh = (col >> 7) & 15;
                const int h = col & 127;              // even
                const int f = h >> 1;
                __nv_bfloat16* dh = (part == 0) ? g_Qh : (part == 1) ? g_Kh2 : g_Vh2;
                __nv_bfloat16* dl = (part == 0) ? g_Ql : (part == 1) ? g_Kl2 : g_Vl2;
#pragma unroll
                for (int rr = 0; rr < 2; rr++) {
                    const int row = row0 + rr * 8;
                    const int bb = row >> 11, tt = row & 2047;
                    float v0 = acc[mf][nf][rr * 2], v1 = acc[mf][nf][rr * 2 + 1];
                    if (part == 0) {
                        v0 *= 0.08838834764831845f;   // 1/sqrt(128)
                        v1 *= 0.08838834764831845f;
                    } else {
                        const float cs = cosT[tt * FR + f];
                        const float sn = sinT[tt * FR + f];
                        const float r_ = v0 * cs - v1 * sn;
                        const float i_ = v0 * sn + v1 * cs;
                        v0 = r_; v1 = i_;
                    }
                    const size_t idx =
                        ((size_t)((bb << 4) + nh) * Tseq + tt) * HD + h;
                    split_store(dh, dl, idx, v0, v1);
                }
            } else {
#pragma unroll
                for (int rr = 0; rr < 2; rr++) {
                    const int row = row0 + rr * 8;
                    float2* dp = (float2*)&C[(size_t)row * 2048 + col];
                    *dp = make_float2(acc[mf][nf][rr * 2], acc[mf][nf][rr * 2 + 1]);
                }
            }
        }
    }
}

// ---------------------------------------------------------------------------
// Tensor-core flash attention (causal), split-bf16.
// CTA: 128 q rows x 1 head. 8 warps x 16 rows. 64-key tiles, double-buffered.
// QK: Qh*Kh + Ql*Kh + Qh*Kl.  PV: Ph*Vh + Pl*Vh + Ph*Vl.
// ---------------------------------------------------------------------------
#define AT_RS   136                      // padded row stride (bf16)
#define AT_RSB  (AT_RS * 2)              // 272 bytes
#define QT_B    (128 * AT_RSB)           // 34816
#define KVT_B   (64 * AT_RSB)            // 17408
#define ASMEM_BYTES (2 * QT_B + 8 * KVT_B)  // 208896

__global__ void __launch_bounds__(256) attn_tc() {
    extern __shared__ char smem[];
    const uint32_t sb = smem_u32(smem);
    const int b = blockIdx.z, n = blockIdx.y, qt = blockIdx.x;
    const int tid = threadIdx.x;
    const int lane = tid & 31, warp = tid >> 5;
    const int g = lane >> 2, t4 = lane & 3;

    const size_t headoff = (size_t)(b * NHEAD + n) * Tseq * HD;
    const __nv_bfloat16* Qhg = g_Qh + headoff + (size_t)qt * 128 * HD;
    const __nv_bfloat16* Qlg = g_Ql + headoff + (size_t)qt * 128 * HD;

    // Load Q tiles (hi/lo)
    for (int i = tid; i < 2048; i += 256) {
        const int row = i >> 4, q = i & 15;
        const uint32_t so = (uint32_t)row * AT_RSB + q * 16;
        const size_t go = (size_t)row * HD + q * 8;
        CP16(sb + so, Qhg + go);
        CP16(sb + QT_B + so, Qlg + go);
    }
    CP_COMMIT();

    auto load_kv = [&](int stage, int kt) {
        const uint32_t base = sb + 2 * QT_B + stage * (4 * KVT_B);
        const size_t koff = headoff + (size_t)kt * 64 * HD;
        const __nv_bfloat16* Khp = g_Kh2 + koff;
        const __nv_bfloat16* Klp = g_Kl2 + koff;
        const __nv_bfloat16* Vhp = g_Vh2 + koff;
        const __nv_bfloat16* Vlp = g_Vl2 + koff;
        for (int i = tid; i < 1024; i += 256) {
            const int row = i >> 4, q = i & 15;
            const uint32_t so = (uint32_t)row * AT_RSB + q * 16;
            const size_t go = (size_t)row * HD + q * 8;
            CP16(base + 0 * KVT_B + so, Khp + go);
            CP16(base + 1 * KVT_B + so, Klp + go);
            CP16(base + 2 * KVT_B + so, Vhp + go);
            CP16(base + 3 * KVT_B + so, Vlp + go);
        }
        CP_COMMIT();
    };

    load_kv(0, 0);
    const int ntiles = 2 * qt + 2;

    float o[16][4];
#pragma unroll
    for (int f = 0; f < 16; f++)
#pragma unroll
        for (int r = 0; r < 4; r++) o[f][r] = 0.f;
    float m0r = -1e30f, m1r = -1e30f, l0 = 0.f, l1 = 0.f;

    const int qrow0 = qt * 128 + warp * 16;  // warp's first q row
    // Q a-frag lane address (within Q tile), + ks*32 bytes per k-step
    const uint32_t qa = sb + (uint32_t)(warp * 16 + (lane & 15)) * AT_RSB +
                        (lane >> 4) * 16;
    const int kb_row = (lane & 7) + ((lane >> 4) << 3);
    const int kb_colb = ((lane >> 3) & 1) * 16;
    const int v_row = lane & 15;
    const int v_colb = (lane >> 4) * 16;

    for (int kt = 0; kt < ntiles; kt++) {
        if (kt + 1 < ntiles) {
            load_kv((kt + 1) & 1, kt + 1);
            CP_WAIT1();
        } else {
            CP_WAIT0();
        }
        __syncthreads();

        const uint32_t base = sb + 2 * QT_B + (kt & 1) * (4 * KVT_B);
        const uint32_t tKh = base, tKl = base + KVT_B;
        const uint32_t tVh = base + 2 * KVT_B, tVl = base + 3 * KVT_B;

        // ---- S = Q K^T (3 split passes) ----
        float s[8][4];
#pragma unroll
        for (int nf = 0; nf < 8; nf++)
#pragma unroll
            for (int r = 0; r < 4; r++) s[nf][r] = 0.f;

#pragma unroll
        for (int ks = 0; ks < 8; ks++) {
            uint32_t aH[4], aL[4];
            LDSM4(aH, qa + ks * 32);
            LDSM4(aL, qa + QT_B + ks * 32);
#pragma unroll
            for (int kn = 0; kn < 4; kn++) {
                uint32_t rH[4], rL[4];
                const uint32_t ko = (uint32_t)(kn * 16 + kb_row) * AT_RSB +
                                    ks * 32 + kb_colb;
                LDSM4(rH, tKh + ko);
                LDSM4(rL, tKl + ko);
                mma_16816(s[2 * kn], aH, rH);
                mma_16816(s[2 * kn + 1], aH, rH + 2);
                mma_16816(s[2 * kn], aL, rH);
                mma_16816(s[2 * kn + 1], aL, rH + 2);
                mma_16816(s[2 * kn], aH, rL);
                mma_16816(s[2 * kn + 1], aH, rL + 2);
            }
        }

        // ---- causal mask ----
        if (kt * 64 + 63 > qrow0) {
            const int r0 = qrow0 + g, r1 = r0 + 8;
#pragma unroll
            for (int nf = 0; nf < 8; nf++) {
                const int k0 = kt * 64 + nf * 8 + 2 * t4;
                if (k0 > r0) s[nf][0] = -1e30f;
                if (k0 + 1 > r0) s[nf][1] = -1e30f;
                if (k0 > r1) s[nf][2] = -1e30f;
                if (k0 + 1 > r1) s[nf][3] = -1e30f;
            }
        }

        // ---- online softmax ----
        float tm0 = -1e30f, tm1 = -1e30f;
#pragma unroll
        for (int nf = 0; nf < 8; nf++) {
            tm0 = fmaxf(tm0, fmaxf(s[nf][0], s[nf][1]));
            tm1 = fmaxf(tm1, fmaxf(s[nf][2], s[nf][3]));
        }
        tm0 = fmaxf(tm0, __shfl_xor_sync(0xffffffffu, tm0, 1));
        tm0 = fmaxf(tm0, __shfl_xor_sync(0xffffffffu, tm0, 2));
        tm1 = fmaxf(tm1, __shfl_xor_sync(0xffffffffu, tm1, 1));
        tm1 = fmaxf(tm1, __shfl_xor_sync(0xffffffffu, tm1, 2));
        const float nm0 = fmaxf(m0r, tm0), nm1 = fmaxf(m1r, tm1);
        const float cr0 = __expf(m0r - nm0), cr1 = __expf(m1r - nm1);
        m0r = nm0; m1r = nm1;
        float ps0 = 0.f, ps1 = 0.f;
#pragma unroll
        for (int nf = 0; nf < 8; nf++) {
            s[nf][0] = __expf(s[nf][0] - m0r);
            s[nf][1] = __expf(s[nf][1] - m0r);
            s[nf][2] = __expf(s[nf][2] - m1r);
            s[nf][3] = __expf(s[nf][3] - m1r);
            ps0 += s[nf][0] + s[nf][1];
            ps1 += s[nf][2] + s[nf][3];
        }
        ps0 += __shfl_xor_sync(0xffffffffu, ps0, 1);
        ps0 += __shfl_xor_sync(0xffffffffu, ps0, 2);
        ps1 += __shfl_xor_sync(0xffffffffu, ps1, 1);
        ps1 += __shfl_xor_sync(0xffffffffu, ps1, 2);
        l0 = l0 * cr0 + ps0;
        l1 = l1 * cr1 + ps1;
#pragma unroll
        for (int f = 0; f < 16; f++) {
            o[f][0] *= cr0; o[f][1] *= cr0;
            o[f][2] *= cr1; o[f][3] *= cr1;
        }

        // ---- O += P V (3 split passes) ----
#pragma unroll
        for (int j = 0; j < 4; j++) {
            uint32_t aPh[4], aPl[4];
#pragma unroll
            for (int hh = 0; hh < 2; hh++) {  // s-frags 2j, 2j+1
                const float* sp = s[2 * j + hh];
#pragma unroll
                for (int rr = 0; rr < 2; rr++) {
                    const float x = sp[rr * 2], y = sp[rr * 2 + 1];
                    const uint32_t hp = pack_bf16x2(x, y);
                    aPh[hh * 2 + rr] = hp;
                    const __nv_bfloat162 hb = *(const __nv_bfloat162*)&hp;
                    aPl[hh * 2 + rr] = pack_bf16x2(
                        x - __bfloat162float(hb.x), y - __bfloat162float(hb.y));
                }
            }
#pragma unroll
            for (int dn = 0; dn < 8; dn++) {
                uint32_t vH[4], vL[4];
                const uint32_t vo = (uint32_t)(j * 16 + v_row) * AT_RSB +
                                    dn * 32 + v_colb;
                LDSM4T(vH, tVh + vo);
                LDSM4T(vL, tVl + vo);
                mma_16816(o[2 * dn], aPh, vH);
                mma_16816(o[2 * dn + 1], aPh, vH + 2);
                mma_16816(o[2 * dn], aPl, vH);
                mma_16816(o[2 * dn + 1], aPl, vH + 2);
                mma_16816(o[2 * dn], aPh, vL);
                mma_16816(o[2 * dn + 1], aPh, vL + 2);
            }
        }
        __syncthreads();
    }

    // ---- finalize: o /= l, split-store to g_Oh/g_Ol [B,T,D] ----
    const float inv0 = 1.f / l0, inv1 = 1.f / l1;
    const int r0 = qrow0 + g, r1 = r0 + 8;
#pragma unroll
    for (int f = 0; f < 16; f++) {
        const int col = n * HD + f * 8 + t4 * 2;
        const size_t i0 = ((size_t)(b * Tseq + r0)) * Dmodel + col;
        const size_t i1 = ((size_t)(b * Tseq + r1)) * Dmodel + col;
        split_store(g_Oh, g_Ol, i0, o[f][0] * inv0, o[f][1] * inv0);
        split_store(g_Oh, g_Ol, i1, o[f][2] * inv1, o[f][3] * inv1);
    }
}

// ---------------------------------------------------------------------------
// Host launcher (graph-capturable: kernel launches only)
// Inputs: 0=x, 1=mask(unused: exact causal tril), 2=cos, 3=sin, 4=w_attn, 5=w_out
// ---------------------------------------------------------------------------
extern "C" void kernel_launch(void* const* d_in, const int* in_sizes, int n_in,
                              void* d_out, int out_size) {
    const float* x = (const float*)d_in[0];
    const float* cosT = (const float*)d_in[2];
    const float* sinT = (const float*)d_in[3];
    const float* w_attn = (const float*)d_in[4];
    const float* w_out = (const float*)d_in[5];
    float* out = (float*)d_out;

    cudaFuncSetAttribute(gemm_tc<0>, cudaFuncAttributeMaxDynamicSharedMemorySize,
                         GSMEM_BYTES);
    cudaFuncSetAttribute(gemm_tc<1>, cudaFuncAttributeMaxDynamicSharedMemorySize,
                         GSMEM_BYTES);
    cudaFuncSetAttribute(attn_tc, cudaFuncAttributeMaxDynamicSharedMemorySize,
                         ASMEM_BYTES);

    __nv_bfloat16 *pXh, *pXl, *pWh, *pWl, *pWOh, *pWOl, *pOh, *pOl;
    cudaGetSymbolAddress((void**)&pXh, g_Xh);
    cudaGetSymbolAddress((void**)&pXl, g_Xl);
    cudaGetSymbolAddress((void**)&pWh, g_Wh);
    cudaGetSymbolAddress((void**)&pWl, g_Wl);
    cudaGetSymbolAddress((void**)&pWOh, g_WOh);
    cudaGetSymbolAddress((void**)&pWOl, g_WOl);
    cudaGetSymbolAddress((void**)&pOh, g_Oh);
    cudaGetSymbolAddress((void**)&pOl, g_Ol);

    // Operand preparation
    const int n4x = (Bsz * Tseq * Dmodel) / 4;
    convert_split<<<n4x / 256, 256>>>(x, pXh, pXl, n4x);
    convert_wT<<<dim3(3 * Dmodel / 32, Dmodel / 32), dim3(32, 8)>>>(
        w_attn, pWh, pWl, Dmodel, 3 * Dmodel);
    convert_wT<<<dim3(Dmodel / 32, Dmodel / 32), dim3(32, 8)>>>(
        w_out, pWOh, pWOl, Dmodel, Dmodel);

    // QKV projection + fused scale/rope/split -> split Q/K/V [B,N,T,H]
    gemm_tc<0><<<dim3(48, 32), 256, GSMEM_BYTES>>>(pXh, pXl, pWh, pWl, nullptr,
                                                   cosT, sinT);

    // Tensor-core causal flash attention -> split O [B,T,D]
    attn_tc<<<dim3(Tseq / 128, NHEAD, Bsz), 256, ASMEM_BYTES>>>();

    // Output projection -> d_out
    gemm_tc<1><<<dim3(16, 32), 256, GSMEM_BYTES>>>(pOh, pOl, pWOh, pWOl, out,
                                                   nullptr, nullptr);
}

// round 7
// speedup vs baseline: 4.0532x; 1.1342x over previous
#include <cuda_runtime.h>
#include <cuda_bf16.h>
#include <cstdint>

// Problem constants
#define Bsz    2
#define Tseq   2048
#define Dmodel 2048
#define NHEAD  16
#define HD     128
#define FR     64

// ---------------------------------------------------------------------------
// Scratch (static __device__ — no allocations allowed)
// ---------------------------------------------------------------------------
__device__ __nv_bfloat16 g_Xh[(size_t)Bsz * Tseq * Dmodel];
__device__ __nv_bfloat16 g_Xl[(size_t)Bsz * Tseq * Dmodel];
__device__ __nv_bfloat16 g_Wh[(size_t)3 * Dmodel * Dmodel];   // w_attn^T [6144][2048]
__device__ __nv_bfloat16 g_Wl[(size_t)3 * Dmodel * Dmodel];
__device__ __nv_bfloat16 g_WOh[(size_t)Dmodel * Dmodel];      // w_out^T [2048][2048]
__device__ __nv_bfloat16 g_WOl[(size_t)Dmodel * Dmodel];
__device__ __nv_bfloat16 g_Qh[(size_t)Bsz * NHEAD * Tseq * HD];
__device__ __nv_bfloat16 g_Ql[(size_t)Bsz * NHEAD * Tseq * HD];
__device__ __nv_bfloat16 g_Kh2[(size_t)Bsz * NHEAD * Tseq * HD];
__device__ __nv_bfloat16 g_Kl2[(size_t)Bsz * NHEAD * Tseq * HD];
__device__ __nv_bfloat16 g_Vh2[(size_t)Bsz * NHEAD * Tseq * HD];
__device__ __nv_bfloat16 g_Vl2[(size_t)Bsz * NHEAD * Tseq * HD];
__device__ __nv_bfloat16 g_Oh[(size_t)Bsz * Tseq * Dmodel];
__device__ __nv_bfloat16 g_Ol[(size_t)Bsz * Tseq * Dmodel];

// ---------------------------------------------------------------------------
// mma.sync / ldmatrix / cp.async helpers (sm_80+ baseline PTX)
// ---------------------------------------------------------------------------
__device__ __forceinline__ uint32_t smem_u32(const void* p) {
    uint32_t a;
    asm("{ .reg .u64 t; cvta.to.shared.u64 t, %1; cvt.u32.u64 %0, t; }"
        : "=r"(a) : "l"(p));
    return a;
}

#define LDSM4(r, addr) \
    asm volatile("ldmatrix.sync.aligned.m8n8.x4.shared.b16 {%0,%1,%2,%3}, [%4];" \
                 : "=r"((r)[0]), "=r"((r)[1]), "=r"((r)[2]), "=r"((r)[3]) \
                 : "r"(addr))
#define LDSM4T(r, addr) \
    asm volatile("ldmatrix.sync.aligned.m8n8.x4.trans.shared.b16 {%0,%1,%2,%3}, [%4];" \
                 : "=r"((r)[0]), "=r"((r)[1]), "=r"((r)[2]), "=r"((r)[3]) \
                 : "r"(addr))

__device__ __forceinline__ void mma_16816(float* c, const uint32_t* a,
                                          const uint32_t* b) {
    asm volatile(
        "mma.sync.aligned.m16n8k16.row.col.f32.bf16.bf16.f32 "
        "{%0,%1,%2,%3}, {%4,%5,%6,%7}, {%8,%9}, {%0,%1,%2,%3};"
        : "+f"(c[0]), "+f"(c[1]), "+f"(c[2]), "+f"(c[3])
        : "r"(a[0]), "r"(a[1]), "r"(a[2]), "r"(a[3]), "r"(b[0]), "r"(b[1]));
}

#define CP16(dst, src) \
    asm volatile("cp.async.cg.shared.global [%0], [%1], 16;" \
                 :: "r"(dst), "l"(src) : "memory")
#define CP_COMMIT() asm volatile("cp.async.commit_group;" ::: "memory")
#define CP_WAIT1()  asm volatile("cp.async.wait_group 1;" ::: "memory")
#define CP_WAIT0()  asm volatile("cp.async.wait_group 0;" ::: "memory")

__device__ __forceinline__ uint32_t pack_bf16x2(float x, float y) {
    __nv_bfloat162 h = __halves2bfloat162(__float2bfloat16(x), __float2bfloat16(y));
    return *(uint32_t*)&h;
}
__device__ __forceinline__ void split_store(__nv_bfloat16* hi, __nv_bfloat16* lo,
                                            size_t idx, float v0, float v1) {
    __nv_bfloat16 h0 = __float2bfloat16(v0);
    __nv_bfloat16 h1 = __float2bfloat16(v1);
    __nv_bfloat16 l0 = __float2bfloat16(v0 - __bfloat162float(h0));
    __nv_bfloat16 l1 = __float2bfloat16(v1 - __bfloat162float(h1));
    *(__nv_bfloat162*)&hi[idx] = __halves2bfloat162(h0, h1);
    *(__nv_bfloat162*)&lo[idx] = __halves2bfloat162(l0, l1);
}

// ---------------------------------------------------------------------------
// fp32 -> (bf16 hi, bf16 lo) elementwise split
// ---------------------------------------------------------------------------
__global__ void convert_split(const float* __restrict__ in,
                              __nv_bfloat16* __restrict__ hi,
                              __nv_bfloat16* __restrict__ lo, int n4) {
    const int i = blockIdx.x * blockDim.x + threadIdx.x;
    if (i >= n4) return;
    float4 a = ((const float4*)in)[i];
    __nv_bfloat16 h0 = __float2bfloat16(a.x);
    __nv_bfloat16 h1 = __float2bfloat16(a.y);
    __nv_bfloat16 h2 = __float2bfloat16(a.z);
    __nv_bfloat16 h3 = __float2bfloat16(a.w);
    __nv_bfloat16 l0 = __float2bfloat16(a.x - __bfloat162float(h0));
    __nv_bfloat16 l1 = __float2bfloat16(a.y - __bfloat162float(h1));
    __nv_bfloat16 l2 = __float2bfloat16(a.z - __bfloat162float(h2));
    __nv_bfloat16 l3 = __float2bfloat16(a.w - __bfloat162float(h3));
    ((__nv_bfloat162*)hi)[i * 2 + 0] = __halves2bfloat162(h0, h1);
    ((__nv_bfloat162*)hi)[i * 2 + 1] = __halves2bfloat162(h2, h3);
    ((__nv_bfloat162*)lo)[i * 2 + 0] = __halves2bfloat162(l0, l1);
    ((__nv_bfloat162*)lo)[i * 2 + 1] = __halves2bfloat162(l2, l3);
}

// ---------------------------------------------------------------------------
// Transpose W [K, Ncols] (row-major) -> Wt [Ncols, K] with hi/lo bf16 split
// ---------------------------------------------------------------------------
__global__ void convert_wT(const float* __restrict__ W,
                           __nv_bfloat16* __restrict__ Th,
                           __nv_bfloat16* __restrict__ Tl, int K, int Ncols) {
    __shared__ float s[32][33];
    const int n0 = blockIdx.x * 32, k0 = blockIdx.y * 32;
    const int tx = threadIdx.x, ty = threadIdx.y;  // (32, 8)
#pragma unroll
    for (int i = 0; i < 4; i++)
        s[ty + i * 8][tx] = W[(size_t)(k0 + ty + i * 8) * Ncols + n0 + tx];
    __syncthreads();
#pragma unroll
    for (int i = 0; i < 4; i++) {
        const float a = s[tx][ty + i * 8];
        const __nv_bfloat16 h = __float2bfloat16(a);
        const __nv_bfloat16 l = __float2bfloat16(a - __bfloat162float(h));
        const size_t o = (size_t)(n0 + ty + i * 8) * K + k0 + tx;
        Th[o] = h;
        Tl[o] = l;
    }
}

// ---------------------------------------------------------------------------
// mma.sync split-bf16 GEMM. MODE 0: QKV proj with fused scale(Q)/rope(K,V)
// and split-bf16 scatter to [B,N,T,H]. MODE 1: out-proj -> d_out (fp32).
// Pass order Ah*Bh -> Ah*Bl -> Al*Bh keeps bH live and cuts A-fragment
// reloads; __launch_bounds__(256,2) caps regs at 128 for 2 CTAs/SM.
// ---------------------------------------------------------------------------
#define RSTRIDE 40
#define TILE_B  (128 * RSTRIDE * 2)
#define STAGE_B (4 * TILE_B)
#define GSMEM_BYTES (2 * STAGE_B)

template <int MODE>
__global__ void __launch_bounds__(256, 2) gemm_tc(
    const __nv_bfloat16* __restrict__ Ah, const __nv_bfloat16* __restrict__ Al,
    const __nv_bfloat16* __restrict__ Bh, const __nv_bfloat16* __restrict__ Bl,
    float* __restrict__ C,
    const float* __restrict__ cosT, const float* __restrict__ sinT) {
    extern __shared__ char smem[];
    const uint32_t sb = smem_u32(smem);

    const int tid = threadIdx.x;
    const int lane = tid & 31, warp = tid >> 5;
    const int m0 = blockIdx.y * 128, c0 = blockIdx.x * 128;
    const int wm = (warp & 1) * 64, wn = (warp >> 1) * 32;

    const int a_row = wm + (lane & 15);
    const int a_colb = (lane >> 4) * 16;
    const int b_row = wn + (lane & 7) + ((lane >> 4) << 3);
    const int b_colb = ((lane >> 3) & 1) * 16;

    const __nv_bfloat16* Ah0 = Ah + (size_t)m0 * 2048;
    const __nv_bfloat16* Al0 = Al + (size_t)m0 * 2048;
    const __nv_bfloat16* Bh0 = Bh + (size_t)c0 * 2048;
    const __nv_bfloat16* Bl0 = Bl + (size_t)c0 * 2048;

    float acc[4][4][4];
#pragma unroll
    for (int i = 0; i < 4; i++)
#pragma unroll
        for (int j = 0; j < 4; j++)
#pragma unroll
            for (int r = 0; r < 4; r++) acc[i][j][r] = 0.f;

    auto load_stage = [&](int stage, int kc) {
        const uint32_t s0 = sb + stage * STAGE_B;
        const size_t ko = (size_t)kc * 32;
#pragma unroll
        for (int h = 0; h < 2; h++) {
            const int cch = tid + h * 256;
            const int row = cch >> 2, q = cch & 3;
            const uint32_t so = (uint32_t)row * (RSTRIDE * 2) + q * 16;
            const size_t go = (size_t)row * 2048 + ko + q * 8;
            CP16(s0 + 0 * TILE_B + so, Ah0 + go);
            CP16(s0 + 1 * TILE_B + so, Al0 + go);
            CP16(s0 + 2 * TILE_B + so, Bh0 + go);
            CP16(s0 + 3 * TILE_B + so, Bl0 + go);
        }
        CP_COMMIT();
    };

    load_stage(0, 0);

    for (int c = 0; c < 64; c++) {
        if (c < 63) {
            load_stage((c + 1) & 1, c + 1);
            CP_WAIT1();
        } else {
            CP_WAIT0();
        }
        __syncthreads();

        const uint32_t st = sb + (c & 1) * STAGE_B;
        const uint32_t tAh = st + 0 * TILE_B, tAl = st + 1 * TILE_B;
        const uint32_t tBh = st + 2 * TILE_B, tBl = st + 3 * TILE_B;

#pragma unroll
        for (int t = 0; t < 2; t++) {
            const int tcb = t * 32;
            uint32_t aF[4][4], bH[4][2], bL[4][2];

            // load aH + bH, pass 1: Ah * Bh
#pragma unroll
            for (int mf = 0; mf < 4; mf++)
                LDSM4(aF[mf], tAh + (a_row + mf * 16) * (RSTRIDE * 2) + tcb + a_colb);
#pragma unroll
            for (int nf2 = 0; nf2 < 2; nf2++) {
                uint32_t r[4];
                LDSM4(r, tBh + (b_row + nf2 * 16) * (RSTRIDE * 2) + tcb + b_colb);
                bH[nf2 * 2][0] = r[0]; bH[nf2 * 2][1] = r[1];
                bH[nf2 * 2 + 1][0] = r[2]; bH[nf2 * 2 + 1][1] = r[3];
            }
#pragma unroll
            for (int mf = 0; mf < 4; mf++)
#pragma unroll
                for (int nf = 0; nf < 4; nf++) mma_16816(acc[mf][nf], aF[mf], bH[nf]);

            // load bL, pass 2: Ah * Bl (aH still live)
#pragma unroll
            for (int nf2 = 0; nf2 < 2; nf2++) {
                uint32_t r[4];
                LDSM4(r, tBl + (b_row + nf2 * 16) * (RSTRIDE * 2) + tcb + b_colb);
                bL[nf2 * 2][0] = r[0]; bL[nf2 * 2][1] = r[1];
                bL[nf2 * 2 + 1][0] = r[2]; bL[nf2 * 2 + 1][1] = r[3];
            }
#pragma unroll
            for (int mf = 0; mf < 4; mf++)
#pragma unroll
                for (int nf = 0; nf < 4; nf++) mma_16816(acc[mf][nf], aF[mf], bL[nf]);

            // load aL (overwrites aF), pass 3: Al * Bh (bH still live)
#pragma unroll
            for (int mf = 0; mf < 4; mf++)
                LDSM4(aF[mf], tAl + (a_row + mf * 16) * (RSTRIDE * 2) + tcb + a_colb);
#pragma unroll
            for (int mf = 0; mf < 4; mf++)
#pragma unroll
                for (int nf = 0; nf < 4; nf++) mma_16816(acc[mf][nf], aF[mf], bH[nf]);
        }
        __syncthreads();
    }

    // Epilogue
    const int g = lane >> 2, tg = lane & 3;
#pragma unroll
    for (int mf = 0; mf < 4; mf++) {
#pragma unroll
        for (int nf = 0; nf < 4; nf++) {
            const int row0 = m0 + wm + mf * 16 + g;
            const int col = c0 + wn + nf * 8 + tg * 2;  // even
            if (MODE == 0) {
                const int part = col >> 11;           // 0=Q,1=K,2=V
                const int nh = (col >> 7) & 15;
                const int h = col & 127;              // even
                const int f = h >> 1;
                __nv_bfloat16* dh = (part == 0) ? g_Qh : (part == 1) ? g_Kh2 : g_Vh2;
                __nv_bfloat16* dl = (part == 0) ? g_Ql : (part == 1) ? g_Kl2 : g_Vl2;
#pragma unroll
                for (int rr = 0; rr < 2; rr++) {
                    const int row = row0 + rr * 8;
                    const int bb = row >> 11, tt = row & 2047;
                    float v0 = acc[mf][nf][rr * 2], v1 = acc[mf][nf][rr * 2 + 1];
                    if (part == 0) {
                        v0 *= 0.08838834764831845f;   // 1/sqrt(128)
                        v1 *= 0.08838834764831845f;
                    } else {
                        const float cs = cosT[tt * FR + f];
                        const float sn = sinT[tt * FR + f];
                        const float r_ = v0 * cs - v1 * sn;
                        const float i_ = v0 * sn + v1 * cs;
                        v0 = r_; v1 = i_;
                    }
                    const size_t idx =
                        ((size_t)((bb << 4) + nh) * Tseq + tt) * HD + h;
                    split_store(dh, dl, idx, v0, v1);
                }
            } else {
#pragma unroll
                for (int rr = 0; rr < 2; rr++) {
                    const int row = row0 + rr * 8;
                    float2* dp = (float2*)&C[(size_t)row * 2048 + col];
                    *dp = make_float2(acc[mf][nf][rr * 2], acc[mf][nf][rr * 2 + 1]);
                }
            }
        }
    }
}

// ---------------------------------------------------------------------------
// Tensor-core flash attention (causal), split-bf16 — unchanged from R6.
// ---------------------------------------------------------------------------
#define AT_RS   136
#define AT_RSB  (AT_RS * 2)
#define QT_B    (128 * AT_RSB)
#define KVT_B   (64 * AT_RSB)
#define ASMEM_BYTES (2 * QT_B + 8 * KVT_B)

__global__ void __launch_bounds__(256) attn_tc() {
    extern __shared__ char smem[];
    const uint32_t sb = smem_u32(smem);
    const int b = blockIdx.z, n = blockIdx.y, qt = blockIdx.x;
    const int tid = threadIdx.x;
    const int lane = tid & 31, warp = tid >> 5;
    const int g = lane >> 2, t4 = lane & 3;

    const size_t headoff = (size_t)(b * NHEAD + n) * Tseq * HD;
    const __nv_bfloat16* Qhg = g_Qh + headoff + (size_t)qt * 128 * HD;
    const __nv_bfloat16* Qlg = g_Ql + headoff + (size_t)qt * 128 * HD;

    for (int i = tid; i < 2048; i += 256) {
        const int row = i >> 4, q = i & 15;
        const uint32_t so = (uint32_t)row * AT_RSB + q * 16;
        const size_t go = (size_t)row * HD + q * 8;
        CP16(sb + so, Qhg + go);
        CP16(sb + QT_B + so, Qlg + go);
    }
    CP_COMMIT();

    auto load_kv = [&](int stage, int kt) {
        const uint32_t base = sb + 2 * QT_B + stage * (4 * KVT_B);
        const size_t koff = headoff + (size_t)kt * 64 * HD;
        const __nv_bfloat16* Khp = g_Kh2 + koff;
        const __nv_bfloat16* Klp = g_Kl2 + koff;
        const __nv_bfloat16* Vhp = g_Vh2 + koff;
        const __nv_bfloat16* Vlp = g_Vl2 + koff;
        for (int i = tid; i < 1024; i += 256) {
            const int row = i >> 4, q = i & 15;
            const uint32_t so = (uint32_t)row * AT_RSB + q * 16;
            const size_t go = (size_t)row * HD + q * 8;
            CP16(base + 0 * KVT_B + so, Khp + go);
            CP16(base + 1 * KVT_B + so, Klp + go);
            CP16(base + 2 * KVT_B + so, Vhp + go);
            CP16(base + 3 * KVT_B + so, Vlp + go);
        }
        CP_COMMIT();
    };

    load_kv(0, 0);
    const int ntiles = 2 * qt + 2;

    float o[16][4];
#pragma unroll
    for (int f = 0; f < 16; f++)
#pragma unroll
        for (int r = 0; r < 4; r++) o[f][r] = 0.f;
    float m0r = -1e30f, m1r = -1e30f, l0 = 0.f, l1 = 0.f;

    const int qrow0 = qt * 128 + warp * 16;
    const uint32_t qa = sb + (uint32_t)(warp * 16 + (lane & 15)) * AT_RSB +
                        (lane >> 4) * 16;
    const int kb_row = (lane & 7) + ((lane >> 4) << 3);
    const int kb_colb = ((lane >> 3) & 1) * 16;
    const int v_row = lane & 15;
    const int v_colb = (lane >> 4) * 16;

    for (int kt = 0; kt < ntiles; kt++) {
        if (kt + 1 < ntiles) {
            load_kv((kt + 1) & 1, kt + 1);
            CP_WAIT1();
        } else {
            CP_WAIT0();
        }
        __syncthreads();

        const uint32_t base = sb + 2 * QT_B + (kt & 1) * (4 * KVT_B);
        const uint32_t tKh = base, tKl = base + KVT_B;
        const uint32_t tVh = base + 2 * KVT_B, tVl = base + 3 * KVT_B;

        float s[8][4];
#pragma unroll
        for (int nf = 0; nf < 8; nf++)
#pragma unroll
            for (int r = 0; r < 4; r++) s[nf][r] = 0.f;

#pragma unroll
        for (int ks = 0; ks < 8; ks++) {
            uint32_t aH[4], aL[4];
            LDSM4(aH, qa + ks * 32);
            LDSM4(aL, qa + QT_B + ks * 32);
#pragma unroll
            for (int kn = 0; kn < 4; kn++) {
                uint32_t rH[4], rL[4];
                const uint32_t ko = (uint32_t)(kn * 16 + kb_row) * AT_RSB +
                                    ks * 32 + kb_colb;
                LDSM4(rH, tKh + ko);
                LDSM4(rL, tKl + ko);
                mma_16816(s[2 * kn], aH, rH);
                mma_16816(s[2 * kn + 1], aH, rH + 2);
                mma_16816(s[2 * kn], aL, rH);
                mma_16816(s[2 * kn + 1], aL, rH + 2);
                mma_16816(s[2 * kn], aH, rL);
                mma_16816(s[2 * kn + 1], aH, rL + 2);
            }
        }

        if (kt * 64 + 63 > qrow0) {
            const int r0 = qrow0 + g, r1 = r0 + 8;
#pragma unroll
            for (int nf = 0; nf < 8; nf++) {
                const int k0 = kt * 64 + nf * 8 + 2 * t4;
                if (k0 > r0) s[nf][0] = -1e30f;
                if (k0 + 1 > r0) s[nf][1] = -1e30f;
                if (k0 > r1) s[nf][2] = -1e30f;
                if (k0 + 1 > r1) s[nf][3] = -1e30f;
            }
        }

        float tm0 = -1e30f, tm1 = -1e30f;
#pragma unroll
        for (int nf = 0; nf < 8; nf++) {
            tm0 = fmaxf(tm0, fmaxf(s[nf][0], s[nf][1]));
            tm1 = fmaxf(tm1, fmaxf(s[nf][2], s[nf][3]));
        }
        tm0 = fmaxf(tm0, __shfl_xor_sync(0xffffffffu, tm0, 1));
        tm0 = fmaxf(tm0, __shfl_xor_sync(0xffffffffu, tm0, 2));
        tm1 = fmaxf(tm1, __shfl_xor_sync(0xffffffffu, tm1, 1));
        tm1 = fmaxf(tm1, __shfl_xor_sync(0xffffffffu, tm1, 2));
        const float nm0 = fmaxf(m0r, tm0), nm1 = fmaxf(m1r, tm1);
        const float cr0 = __expf(m0r - nm0), cr1 = __expf(m1r - nm1);
        m0r = nm0; m1r = nm1;
        float ps0 = 0.f, ps1 = 0.f;
#pragma unroll
        for (int nf = 0; nf < 8; nf++) {
            s[nf][0] = __expf(s[nf][0] - m0r);
            s[nf][1] = __expf(s[nf][1] - m0r);
            s[nf][2] = __expf(s[nf][2] - m1r);
            s[nf][3] = __expf(s[nf][3] - m1r);
            ps0 += s[nf][0] + s[nf][1];
            ps1 += s[nf][2] + s[nf][3];
        }
        ps0 += __shfl_xor_sync(0xffffffffu, ps0, 1);
        ps0 += __shfl_xor_sync(0xffffffffu, ps0, 2);
        ps1 += __shfl_xor_sync(0xffffffffu, ps1, 1);
        ps1 += __shfl_xor_sync(0xffffffffu, ps1, 2);
        l0 = l0 * cr0 + ps0;
        l1 = l1 * cr1 + ps1;
#pragma unroll
        for (int f = 0; f < 16; f++) {
            o[f][0] *= cr0; o[f][1] *= cr0;
            o[f][2] *= cr1; o[f][3] *= cr1;
        }

#pragma unroll
        for (int j = 0; j < 4; j++) {
            uint32_t aPh[4], aPl[4];
#pragma unroll
            for (int hh = 0; hh < 2; hh++) {
                const float* sp = s[2 * j + hh];
#pragma unroll
                for (int rr = 0; rr < 2; rr++) {
                    const float x = sp[rr * 2], y = sp[rr * 2 + 1];
                    const uint32_t hp = pack_bf16x2(x, y);
                    aPh[hh * 2 + rr] = hp;
                    const __nv_bfloat162 hb = *(const __nv_bfloat162*)&hp;
                    aPl[hh * 2 + rr] = pack_bf16x2(
                        x - __bfloat162float(hb.x), y - __bfloat162float(hb.y));
                }
            }
#pragma unroll
            for (int dn = 0; dn < 8; dn++) {
                uint32_t vH[4], vL[4];
                const uint32_t vo = (uint32_t)(j * 16 + v_row) * AT_RSB +
                                    dn * 32 + v_colb;
                LDSM4T(vH, tVh + vo);
                LDSM4T(vL, tVl + vo);
                mma_16816(o[2 * dn], aPh, vH);
                mma_16816(o[2 * dn + 1], aPh, vH + 2);
                mma_16816(o[2 * dn], aPl, vH);
                mma_16816(o[2 * dn + 1], aPl, vH + 2);
                mma_16816(o[2 * dn], aPh, vL);
                mma_16816(o[2 * dn + 1], aPh, vL + 2);
            }
        }
        __syncthreads();
    }

    const float inv0 = 1.f / l0, inv1 = 1.f / l1;
    const int r0 = qrow0 + g, r1 = r0 + 8;
#pragma unroll
    for (int f = 0; f < 16; f++) {
        const int col = n * HD + f * 8 + t4 * 2;
        const size_t i0 = ((size_t)(b * Tseq + r0)) * Dmodel + col;
        const size_t i1 = ((size_t)(b * Tseq + r1)) * Dmodel + col;
        split_store(g_Oh, g_Ol, i0, o[f][0] * inv0, o[f][1] * inv0);
        split_store(g_Oh, g_Ol, i1, o[f][2] * inv1, o[f][3] * inv1);
    }
}

// ---------------------------------------------------------------------------
// Host launcher (graph-capturable: kernel launches only)
// Inputs: 0=x, 1=mask(unused: exact causal tril), 2=cos, 3=sin, 4=w_attn, 5=w_out
// ---------------------------------------------------------------------------
extern "C" void kernel_launch(void* const* d_in, const int* in_sizes, int n_in,
                              void* d_out, int out_size) {
    const float* x = (const float*)d_in[0];
    const float* cosT = (const float*)d_in[2];
    const float* sinT = (const float*)d_in[3];
    const float* w_attn = (const float*)d_in[4];
    const float* w_out = (const float*)d_in[5];
    float* out = (float*)d_out;

    cudaFuncSetAttribute(gemm_tc<0>, cudaFuncAttributeMaxDynamicSharedMemorySize,
                         GSMEM_BYTES);
    cudaFuncSetAttribute(gemm_tc<1>, cudaFuncAttributeMaxDynamicSharedMemorySize,
                         GSMEM_BYTES);
    cudaFuncSetAttribute(attn_tc, cudaFuncAttributeMaxDynamicSharedMemorySize,
                         ASMEM_BYTES);

    __nv_bfloat16 *pXh, *pXl, *pWh, *pWl, *pWOh, *pWOl, *pOh, *pOl;
    cudaGetSymbolAddress((void**)&pXh, g_Xh);
    cudaGetSymbolAddress((void**)&pXl, g_Xl);
    cudaGetSymbolAddress((void**)&pWh, g_Wh);
    cudaGetSymbolAddress((void**)&pWl, g_Wl);
    cudaGetSymbolAddress((void**)&pWOh, g_WOh);
    cudaGetSymbolAddress((void**)&pWOl, g_WOl);
    cudaGetSymbolAddress((void**)&pOh, g_Oh);
    cudaGetSymbolAddress((void**)&pOl, g_Ol);

    // Operand preparation
    const int n4x = (Bsz * Tseq * Dmodel) / 4;
    convert_split<<<n4x / 256, 256>>>(x, pXh, pXl, n4x);
    convert_wT<<<dim3(3 * Dmodel / 32, Dmodel / 32), dim3(32, 8)>>>(
        w_attn, pWh, pWl, Dmodel, 3 * Dmodel);
    convert_wT<<<dim3(Dmodel / 32, Dmodel / 32), dim3(32, 8)>>>(
        w_out, pWOh, pWOl, Dmodel, Dmodel);

    // QKV projection + fused scale/rope/split -> split Q/K/V [B,N,T,H]
    gemm_tc<0><<<dim3(48, 32), 256, GSMEM_BYTES>>>(pXh, pXl, pWh, pWl, nullptr,
                                                   cosT, sinT);

    // Tensor-core causal flash attention -> split O [B,T,D]
    attn_tc<<<dim3(Tseq / 128, NHEAD, Bsz), 256, ASMEM_BYTES>>>();

    // Output projection -> d_out
    gemm_tc<1><<<dim3(16, 32), 256, GSMEM_BYTES>>>(pOh, pOl, pWOh, pWOl, out,
                                                   nullptr, nullptr);
}

// round 8
// speedup vs baseline: 4.0980x; 1.0110x over previous
#include <cuda_runtime.h>
#include <cuda_bf16.h>
#include <cstdint>

// Problem constants
#define Bsz    2
#define Tseq   2048
#define Dmodel 2048
#define NHEAD  16
#define HD     128
#define FR     64

// ---------------------------------------------------------------------------
// Scratch (static __device__ — no allocations allowed)
// ---------------------------------------------------------------------------
__device__ __nv_bfloat16 g_Xh[(size_t)Bsz * Tseq * Dmodel];
__device__ __nv_bfloat16 g_Xl[(size_t)Bsz * Tseq * Dmodel];
__device__ __nv_bfloat16 g_Wh[(size_t)3 * Dmodel * Dmodel];   // w_attn^T [6144][2048]
__device__ __nv_bfloat16 g_Wl[(size_t)3 * Dmodel * Dmodel];
__device__ __nv_bfloat16 g_WOh[(size_t)Dmodel * Dmodel];      // w_out^T [2048][2048]
__device__ __nv_bfloat16 g_WOl[(size_t)Dmodel * Dmodel];
__device__ __nv_bfloat16 g_Qh[(size_t)Bsz * NHEAD * Tseq * HD];
__device__ __nv_bfloat16 g_Ql[(size_t)Bsz * NHEAD * Tseq * HD];
__device__ __nv_bfloat16 g_Kh2[(size_t)Bsz * NHEAD * Tseq * HD];
__device__ __nv_bfloat16 g_Kl2[(size_t)Bsz * NHEAD * Tseq * HD];
__device__ __nv_bfloat16 g_Vh2[(size_t)Bsz * NHEAD * Tseq * HD];
__device__ __nv_bfloat16 g_Vl2[(size_t)Bsz * NHEAD * Tseq * HD];
__device__ __nv_bfloat16 g_Oh[(size_t)Bsz * Tseq * Dmodel];
__device__ __nv_bfloat16 g_Ol[(size_t)Bsz * Tseq * Dmodel];

// ---------------------------------------------------------------------------
// mma.sync / ldmatrix / cp.async helpers (sm_80+ baseline PTX)
// ---------------------------------------------------------------------------
__device__ __forceinline__ uint32_t smem_u32(const void* p) {
    uint32_t a;
    asm("{ .reg .u64 t; cvta.to.shared.u64 t, %1; cvt.u32.u64 %0, t; }"
        : "=r"(a) : "l"(p));
    return a;
}

#define LDSM4(r, addr) \
    asm volatile("ldmatrix.sync.aligned.m8n8.x4.shared.b16 {%0,%1,%2,%3}, [%4];" \
                 : "=r"((r)[0]), "=r"((r)[1]), "=r"((r)[2]), "=r"((r)[3]) \
                 : "r"(addr))
#define LDSM4T(r, addr) \
    asm volatile("ldmatrix.sync.aligned.m8n8.x4.trans.shared.b16 {%0,%1,%2,%3}, [%4];" \
                 : "=r"((r)[0]), "=r"((r)[1]), "=r"((r)[2]), "=r"((r)[3]) \
                 : "r"(addr))

__device__ __forceinline__ void mma_16816(float* c, const uint32_t* a,
                                          const uint32_t* b) {
    asm volatile(
        "mma.sync.aligned.m16n8k16.row.col.f32.bf16.bf16.f32 "
        "{%0,%1,%2,%3}, {%4,%5,%6,%7}, {%8,%9}, {%0,%1,%2,%3};"
        : "+f"(c[0]), "+f"(c[1]), "+f"(c[2]), "+f"(c[3])
        : "r"(a[0]), "r"(a[1]), "r"(a[2]), "r"(a[3]), "r"(b[0]), "r"(b[1]));
}

#define CP16(dst, src) \
    asm volatile("cp.async.cg.shared.global [%0], [%1], 16;" \
                 :: "r"(dst), "l"(src) : "memory")
#define CP_COMMIT() asm volatile("cp.async.commit_group;" ::: "memory")
#define CP_WAIT1()  asm volatile("cp.async.wait_group 1;" ::: "memory")
#define CP_WAIT0()  asm volatile("cp.async.wait_group 0;" ::: "memory")

__device__ __forceinline__ uint32_t pack_bf16x2(float x, float y) {
    __nv_bfloat162 h = __halves2bfloat162(__float2bfloat16(x), __float2bfloat16(y));
    return *(uint32_t*)&h;
}
__device__ __forceinline__ void split_store(__nv_bfloat16* hi, __nv_bfloat16* lo,
                                            size_t idx, float v0, float v1) {
    __nv_bfloat16 h0 = __float2bfloat16(v0);
    __nv_bfloat16 h1 = __float2bfloat16(v1);
    __nv_bfloat16 l0 = __float2bfloat16(v0 - __bfloat162float(h0));
    __nv_bfloat16 l1 = __float2bfloat16(v1 - __bfloat162float(h1));
    *(__nv_bfloat162*)&hi[idx] = __halves2bfloat162(h0, h1);
    *(__nv_bfloat162*)&lo[idx] = __halves2bfloat162(l0, l1);
}

// ---------------------------------------------------------------------------
// fp32 -> (bf16 hi, bf16 lo) elementwise split
// ---------------------------------------------------------------------------
__global__ void convert_split(const float* __restrict__ in,
                              __nv_bfloat16* __restrict__ hi,
                              __nv_bfloat16* __restrict__ lo, int n4) {
    const int i = blockIdx.x * blockDim.x + threadIdx.x;
    if (i >= n4) return;
    float4 a = ((const float4*)in)[i];
    __nv_bfloat16 h0 = __float2bfloat16(a.x);
    __nv_bfloat16 h1 = __float2bfloat16(a.y);
    __nv_bfloat16 h2 = __float2bfloat16(a.z);
    __nv_bfloat16 h3 = __float2bfloat16(a.w);
    __nv_bfloat16 l0 = __float2bfloat16(a.x - __bfloat162float(h0));
    __nv_bfloat16 l1 = __float2bfloat16(a.y - __bfloat162float(h1));
    __nv_bfloat16 l2 = __float2bfloat16(a.z - __bfloat162float(h2));
    __nv_bfloat16 l3 = __float2bfloat16(a.w - __bfloat162float(h3));
    ((__nv_bfloat162*)hi)[i * 2 + 0] = __halves2bfloat162(h0, h1);
    ((__nv_bfloat162*)hi)[i * 2 + 1] = __halves2bfloat162(h2, h3);
    ((__nv_bfloat162*)lo)[i * 2 + 0] = __halves2bfloat162(l0, l1);
    ((__nv_bfloat162*)lo)[i * 2 + 1] = __halves2bfloat162(l2, l3);
}

// ---------------------------------------------------------------------------
// Transpose W [K, Ncols] (row-major) -> Wt [Ncols, K] with hi/lo bf16 split
// ---------------------------------------------------------------------------
__global__ void convert_wT(const float* __restrict__ W,
                           __nv_bfloat16* __restrict__ Th,
                           __nv_bfloat16* __restrict__ Tl, int K, int Ncols) {
    __shared__ float s[32][33];
    const int n0 = blockIdx.x * 32, k0 = blockIdx.y * 32;
    const int tx = threadIdx.x, ty = threadIdx.y;  // (32, 8)
#pragma unroll
    for (int i = 0; i < 4; i++)
        s[ty + i * 8][tx] = W[(size_t)(k0 + ty + i * 8) * Ncols + n0 + tx];
    __syncthreads();
#pragma unroll
    for (int i = 0; i < 4; i++) {
        const float a = s[tx][ty + i * 8];
        const __nv_bfloat16 h = __float2bfloat16(a);
        const __nv_bfloat16 l = __float2bfloat16(a - __bfloat162float(h));
        const size_t o = (size_t)(n0 + ty + i * 8) * K + k0 + tx;
        Th[o] = h;
        Tl[o] = l;
    }
}

// ---------------------------------------------------------------------------
// mma.sync split-bf16 GEMM. MODE 0: QKV proj with fused scale(Q)/rope(K,V)
// and split-bf16 scatter to [B,N,T,H]. MODE 1: out-proj -> d_out (fp32).
// Pass order Ah*Bh -> Ah*Bl -> Al*Bh (bitwise-identical accumulation).
// R8: bL loads hoisted before pass-1 MMAs (16 MMAs of latency cover).
// ---------------------------------------------------------------------------
#define RSTRIDE 40
#define TILE_B  (128 * RSTRIDE * 2)
#define STAGE_B (4 * TILE_B)
#define GSMEM_BYTES (2 * STAGE_B)

template <int MODE>
__global__ void __launch_bounds__(256, 2) gemm_tc(
    const __nv_bfloat16* __restrict__ Ah, const __nv_bfloat16* __restrict__ Al,
    const __nv_bfloat16* __restrict__ Bh, const __nv_bfloat16* __restrict__ Bl,
    float* __restrict__ C,
    const float* __restrict__ cosT, const float* __restrict__ sinT) {
    extern __shared__ char smem[];
    const uint32_t sb = smem_u32(smem);

    const int tid = threadIdx.x;
    const int lane = tid & 31, warp = tid >> 5;
    const int m0 = blockIdx.y * 128, c0 = blockIdx.x * 128;
    const int wm = (warp & 1) * 64, wn = (warp >> 1) * 32;

    const int a_row = wm + (lane & 15);
    const int a_colb = (lane >> 4) * 16;
    const int b_row = wn + (lane & 7) + ((lane >> 4) << 3);
    const int b_colb = ((lane >> 3) & 1) * 16;

    const __nv_bfloat16* Ah0 = Ah + (size_t)m0 * 2048;
    const __nv_bfloat16* Al0 = Al + (size_t)m0 * 2048;
    const __nv_bfloat16* Bh0 = Bh + (size_t)c0 * 2048;
    const __nv_bfloat16* Bl0 = Bl + (size_t)c0 * 2048;

    float acc[4][4][4];
#pragma unroll
    for (int i = 0; i < 4; i++)
#pragma unroll
        for (int j = 0; j < 4; j++)
#pragma unroll
            for (int r = 0; r < 4; r++) acc[i][j][r] = 0.f;

    auto load_stage = [&](int stage, int kc) {
        const uint32_t s0 = sb + stage * STAGE_B;
        const size_t ko = (size_t)kc * 32;
#pragma unroll
        for (int h = 0; h < 2; h++) {
            const int cch = tid + h * 256;
            const int row = cch >> 2, q = cch & 3;
            const uint32_t so = (uint32_t)row * (RSTRIDE * 2) + q * 16;
            const size_t go = (size_t)row * 2048 + ko + q * 8;
            CP16(s0 + 0 * TILE_B + so, Ah0 + go);
            CP16(s0 + 1 * TILE_B + so, Al0 + go);
            CP16(s0 + 2 * TILE_B + so, Bh0 + go);
            CP16(s0 + 3 * TILE_B + so, Bl0 + go);
        }
        CP_COMMIT();
    };

    load_stage(0, 0);

    for (int c = 0; c < 64; c++) {
        if (c < 63) {
            load_stage((c + 1) & 1, c + 1);
            CP_WAIT1();
        } else {
            CP_WAIT0();
        }
        __syncthreads();

        const uint32_t st = sb + (c & 1) * STAGE_B;
        const uint32_t tAh = st + 0 * TILE_B, tAl = st + 1 * TILE_B;
        const uint32_t tBh = st + 2 * TILE_B, tBl = st + 3 * TILE_B;

#pragma unroll
        for (int t = 0; t < 2; t++) {
            const int tcb = t * 32;
            uint32_t aF[4][4], bH[4][2], bL[4][2];

            // load aH, bH, bL up front (bL gets pass-1 MMAs as latency cover)
#pragma unroll
            for (int mf = 0; mf < 4; mf++)
                LDSM4(aF[mf], tAh + (a_row + mf * 16) * (RSTRIDE * 2) + tcb + a_colb);
#pragma unroll
            for (int nf2 = 0; nf2 < 2; nf2++) {
                uint32_t r[4];
                LDSM4(r, tBh + (b_row + nf2 * 16) * (RSTRIDE * 2) + tcb + b_colb);
                bH[nf2 * 2][0] = r[0]; bH[nf2 * 2][1] = r[1];
                bH[nf2 * 2 + 1][0] = r[2]; bH[nf2 * 2 + 1][1] = r[3];
            }
#pragma unroll
            for (int nf2 = 0; nf2 < 2; nf2++) {
                uint32_t r[4];
                LDSM4(r, tBl + (b_row + nf2 * 16) * (RSTRIDE * 2) + tcb + b_colb);
                bL[nf2 * 2][0] = r[0]; bL[nf2 * 2][1] = r[1];
                bL[nf2 * 2 + 1][0] = r[2]; bL[nf2 * 2 + 1][1] = r[3];
            }

            // pass 1: Ah * Bh
#pragma unroll
            for (int mf = 0; mf < 4; mf++)
#pragma unroll
                for (int nf = 0; nf < 4; nf++) mma_16816(acc[mf][nf], aF[mf], bH[nf]);

            // pass 2: Ah * Bl
#pragma unroll
            for (int mf = 0; mf < 4; mf++)
#pragma unroll
                for (int nf = 0; nf < 4; nf++) mma_16816(acc[mf][nf], aF[mf], bL[nf]);

            // load aL (reuses aF), pass 3: Al * Bh
#pragma unroll
            for (int mf = 0; mf < 4; mf++)
                LDSM4(aF[mf], tAl + (a_row + mf * 16) * (RSTRIDE * 2) + tcb + a_colb);
#pragma unroll
            for (int mf = 0; mf < 4; mf++)
#pragma unroll
                for (int nf = 0; nf < 4; nf++) mma_16816(acc[mf][nf], aF[mf], bH[nf]);
        }
        __syncthreads();
    }

    // Epilogue
    const int g = lane >> 2, tg = lane & 3;
#pragma unroll
    for (int mf = 0; mf < 4; mf++) {
#pragma unroll
        for (int nf = 0; nf < 4; nf++) {
            const int row0 = m0 + wm + mf * 16 + g;
            const int col = c0 + wn + nf * 8 + tg * 2;  // even
            if (MODE == 0) {
                const int part = col >> 11;           // 0=Q,1=K,2=V
                const int nh = (col >> 7) & 15;
                const int h = col & 127;              // even
                const int f = h >> 1;
                __nv_bfloat16* dh = (part == 0) ? g_Qh : (part == 1) ? g_Kh2 : g_Vh2;
                __nv_bfloat16* dl = (part == 0) ? g_Ql : (part == 1) ? g_Kl2 : g_Vl2;
#pragma unroll
                for (int rr = 0; rr < 2; rr++) {
                    const int row = row0 + rr * 8;
                    const int bb = row >> 11, tt = row & 2047;
                    float v0 = acc[mf][nf][rr * 2], v1 = acc[mf][nf][rr * 2 + 1];
                    if (part == 0) {
                        v0 *= 0.08838834764831845f;   // 1/sqrt(128)
                        v1 *= 0.08838834764831845f;
                    } else {
                        const float cs = cosT[tt * FR + f];
                        const float sn = sinT[tt * FR + f];
                        const float r_ = v0 * cs - v1 * sn;
                        const float i_ = v0 * sn + v1 * cs;
                        v0 = r_; v1 = i_;
                    }
                    const size_t idx =
                        ((size_t)((bb << 4) + nh) * Tseq + tt) * HD + h;
                    split_store(dh, dl, idx, v0, v1);
                }
            } else {
#pragma unroll
                for (int rr = 0; rr < 2; rr++) {
                    const int row = row0 + rr * 8;
                    float2* dp = (float2*)&C[(size_t)row * 2048 + col];
                    *dp = make_float2(acc[mf][nf][rr * 2], acc[mf][nf][rr * 2 + 1]);
                }
            }
        }
    }
}

// ---------------------------------------------------------------------------
// Tensor-core flash attention (causal), split-bf16.
// R8: K and V fragments double-buffered across inner loops (LDSM for the
// next sub-tile issued before the current sub-tile's MMAs).
// ---------------------------------------------------------------------------
#define AT_RS   136
#define AT_RSB  (AT_RS * 2)
#define QT_B    (128 * AT_RSB)
#define KVT_B   (64 * AT_RSB)
#define ASMEM_BYTES (2 * QT_B + 8 * KVT_B)

__global__ void __launch_bounds__(256) attn_tc() {
    extern __shared__ char smem[];
    const uint32_t sb = smem_u32(smem);
    const int b = blockIdx.z, n = blockIdx.y, qt = blockIdx.x;
    const int tid = threadIdx.x;
    const int lane = tid & 31, warp = tid >> 5;
    const int g = lane >> 2, t4 = lane & 3;

    const size_t headoff = (size_t)(b * NHEAD + n) * Tseq * HD;
    const __nv_bfloat16* Qhg = g_Qh + headoff + (size_t)qt * 128 * HD;
    const __nv_bfloat16* Qlg = g_Ql + headoff + (size_t)qt * 128 * HD;

    for (int i = tid; i < 2048; i += 256) {
        const int row = i >> 4, q = i & 15;
        const uint32_t so = (uint32_t)row * AT_RSB + q * 16;
        const size_t go = (size_t)row * HD + q * 8;
        CP16(sb + so, Qhg + go);
        CP16(sb + QT_B + so, Qlg + go);
    }
    CP_COMMIT();

    auto load_kv = [&](int stage, int kt) {
        const uint32_t base = sb + 2 * QT_B + stage * (4 * KVT_B);
        const size_t koff = headoff + (size_t)kt * 64 * HD;
        const __nv_bfloat16* Khp = g_Kh2 + koff;
        const __nv_bfloat16* Klp = g_Kl2 + koff;
        const __nv_bfloat16* Vhp = g_Vh2 + koff;
        const __nv_bfloat16* Vlp = g_Vl2 + koff;
        for (int i = tid; i < 1024; i += 256) {
            const int row = i >> 4, q = i & 15;
            const uint32_t so = (uint32_t)row * AT_RSB + q * 16;
            const size_t go = (size_t)row * HD + q * 8;
            CP16(base + 0 * KVT_B + so, Khp + go);
            CP16(base + 1 * KVT_B + so, Klp + go);
            CP16(base + 2 * KVT_B + so, Vhp + go);
            CP16(base + 3 * KVT_B + so, Vlp + go);
        }
        CP_COMMIT();
    };

    load_kv(0, 0);
    const int ntiles = 2 * qt + 2;

    float o[16][4];
#pragma unroll
    for (int f = 0; f < 16; f++)
#pragma unroll
        for (int r = 0; r < 4; r++) o[f][r] = 0.f;
    float m0r = -1e30f, m1r = -1e30f, l0 = 0.f, l1 = 0.f;

    const int qrow0 = qt * 128 + warp * 16;
    const uint32_t qa = sb + (uint32_t)(warp * 16 + (lane & 15)) * AT_RSB +
                        (lane >> 4) * 16;
    const int kb_row = (lane & 7) + ((lane >> 4) << 3);
    const int kb_colb = ((lane >> 3) & 1) * 16;
    const int v_row = lane & 15;
    const int v_colb = (lane >> 4) * 16;

    for (int kt = 0; kt < ntiles; kt++) {
        if (kt + 1 < ntiles) {
            load_kv((kt + 1) & 1, kt + 1);
            CP_WAIT1();
        } else {
            CP_WAIT0();
        }
        __syncthreads();

        const uint32_t base = sb + 2 * QT_B + (kt & 1) * (4 * KVT_B);
        const uint32_t tKh = base, tKl = base + KVT_B;
        const uint32_t tVh = base + 2 * KVT_B, tVl = base + 3 * KVT_B;

        float s[8][4];
#pragma unroll
        for (int nf = 0; nf < 8; nf++)
#pragma unroll
            for (int r = 0; r < 4; r++) s[nf][r] = 0.f;

#pragma unroll
        for (int ks = 0; ks < 8; ks++) {
            uint32_t aH[4], aL[4];
            LDSM4(aH, qa + ks * 32);
            LDSM4(aL, qa + QT_B + ks * 32);
            uint32_t rH[2][4], rL[2][4];
            {
                const uint32_t ko0 = (uint32_t)(kb_row)*AT_RSB + ks * 32 + kb_colb;
                LDSM4(rH[0], tKh + ko0);
                LDSM4(rL[0], tKl + ko0);
            }
#pragma unroll
            for (int kn = 0; kn < 4; kn++) {
                const int cur = kn & 1;
                if (kn < 3) {
                    const uint32_t ko =
                        (uint32_t)((kn + 1) * 16 + kb_row) * AT_RSB + ks * 32 + kb_colb;
                    LDSM4(rH[cur ^ 1], tKh + ko);
                    LDSM4(rL[cur ^ 1], tKl + ko);
                }
                mma_16816(s[2 * kn], aH, rH[cur]);
                mma_16816(s[2 * kn + 1], aH, rH[cur] + 2);
                mma_16816(s[2 * kn], aL, rH[cur]);
                mma_16816(s[2 * kn + 1], aL, rH[cur] + 2);
                mma_16816(s[2 * kn], aH, rL[cur]);
                mma_16816(s[2 * kn + 1], aH, rL[cur] + 2);
            }
        }

        if (kt * 64 + 63 > qrow0) {
            const int r0 = qrow0 + g, r1 = r0 + 8;
#pragma unroll
            for (int nf = 0; nf < 8; nf++) {
                const int k0 = kt * 64 + nf * 8 + 2 * t4;
                if (k0 > r0) s[nf][0] = -1e30f;
                if (k0 + 1 > r0) s[nf][1] = -1e30f;
                if (k0 > r1) s[nf][2] = -1e30f;
                if (k0 + 1 > r1) s[nf][3] = -1e30f;
            }
        }

        float tm0 = -1e30f, tm1 = -1e30f;
#pragma unroll
        for (int nf = 0; nf < 8; nf++) {
            tm0 = fmaxf(tm0, fmaxf(s[nf][0], s[nf][1]));
            tm1 = fmaxf(tm1, fmaxf(s[nf][2], s[nf][3]));
        }
        tm0 = fmaxf(tm0, __shfl_xor_sync(0xffffffffu, tm0, 1));
        tm0 = fmaxf(tm0, __shfl_xor_sync(0xffffffffu, tm0, 2));
        tm1 = fmaxf(tm1, __shfl_xor_sync(0xffffffffu, tm1, 1));
        tm1 = fmaxf(tm1, __shfl_xor_sync(0xffffffffu, tm1, 2));
        const float nm0 = fmaxf(m0r, tm0), nm1 = fmaxf(m1r, tm1);
        const float cr0 = __expf(m0r - nm0), cr1 = __expf(m1r - nm1);
        m0r = nm0; m1r = nm1;
        float ps0 = 0.f, ps1 = 0.f;
#pragma unroll
        for (int nf = 0; nf < 8; nf++) {
            s[nf][0] = __expf(s[nf][0] - m0r);
            s[nf][1] = __expf(s[nf][1] - m0r);
            s[nf][2] = __expf(s[nf][2] - m1r);
            s[nf][3] = __expf(s[nf][3] - m1r);
            ps0 += s[nf][0] + s[nf][1];
            ps1 += s[nf][2] + s[nf][3];
        }
        ps0 += __shfl_xor_sync(0xffffffffu, ps0, 1);
        ps0 += __shfl_xor_sync(0xffffffffu, ps0, 2);
        ps1 += __shfl_xor_sync(0xffffffffu, ps1, 1);
        ps1 += __shfl_xor_sync(0xffffffffu, ps1, 2);
        l0 = l0 * cr0 + ps0;
        l1 = l1 * cr1 + ps1;
#pragma unroll
        for (int f = 0; f < 16; f++) {
            o[f][0] *= cr0; o[f][1] *= cr0;
            o[f][2] *= cr1; o[f][3] *= cr1;
        }

#pragma unroll
        for (int j = 0; j < 4; j++) {
            uint32_t aPh[4], aPl[4];
#pragma unroll
            for (int hh = 0; hh < 2; hh++) {
                const float* sp = s[2 * j + hh];
#pragma unroll
                for (int rr = 0; rr < 2; rr++) {
                    const float x = sp[rr * 2], y = sp[rr * 2 + 1];
                    const uint32_t hp = pack_bf16x2(x, y);
                    aPh[hh * 2 + rr] = hp;
                    const __nv_bfloat162 hb = *(const __nv_bfloat162*)&hp;
                    aPl[hh * 2 + rr] = pack_bf16x2(
                        x - __bfloat162float(hb.x), y - __bfloat162float(hb.y));
                }
            }
            uint32_t vH[2][4], vL[2][4];
            {
                const uint32_t vo0 = (uint32_t)(j * 16 + v_row) * AT_RSB + v_colb;
                LDSM4T(vH[0], tVh + vo0);
                LDSM4T(vL[0], tVl + vo0);
            }
#pragma unroll
            for (int dn = 0; dn < 8; dn++) {
                const int cur = dn & 1;
                if (dn < 7) {
                    const uint32_t vo = (uint32_t)(j * 16 + v_row) * AT_RSB +
                                        (dn + 1) * 32 + v_colb;
                    LDSM4T(vH[cur ^ 1], tVh + vo);
                    LDSM4T(vL[cur ^ 1], tVl + vo);
                }
                mma_16816(o[2 * dn], aPh, vH[cur]);
                mma_16816(o[2 * dn + 1], aPh, vH[cur] + 2);
                mma_16816(o[2 * dn], aPl, vH[cur]);
                mma_16816(o[2 * dn + 1], aPl, vH[cur] + 2);
                mma_16816(o[2 * dn], aPh, vL[cur]);
                mma_16816(o[2 * dn + 1], aPh, vL[cur] + 2);
            }
        }
        __syncthreads();
    }

    const float inv0 = 1.f / l0, inv1 = 1.f / l1;
    const int r0 = qrow0 + g, r1 = r0 + 8;
#pragma unroll
    for (int f = 0; f < 16; f++) {
        const int col = n * HD + f * 8 + t4 * 2;
        const size_t i0 = ((size_t)(b * Tseq + r0)) * Dmodel + col;
        const size_t i1 = ((size_t)(b * Tseq + r1)) * Dmodel + col;
        split_store(g_Oh, g_Ol, i0, o[f][0] * inv0, o[f][1] * inv0);
        split_store(g_Oh, g_Ol, i1, o[f][2] * inv1, o[f][3] * inv1);
    }
}

// ---------------------------------------------------------------------------
// Host launcher (graph-capturable: kernel launches only)
// Inputs: 0=x, 1=mask(unused: exact causal tril), 2=cos, 3=sin, 4=w_attn, 5=w_out
// ---------------------------------------------------------------------------
extern "C" void kernel_launch(void* const* d_in, const int* in_sizes, int n_in,
                              void* d_out, int out_size) {
    const float* x = (const float*)d_in[0];
    const float* cosT = (const float*)d_in[2];
    const float* sinT = (const float*)d_in[3];
    const float* w_attn = (const float*)d_in[4];
    const float* w_out = (const float*)d_in[5];
    float* out = (float*)d_out;

    cudaFuncSetAttribute(gemm_tc<0>, cudaFuncAttributeMaxDynamicSharedMemorySize,
                         GSMEM_BYTES);
    cudaFuncSetAttribute(gemm_tc<1>, cudaFuncAttributeMaxDynamicSharedMemorySize,
                         GSMEM_BYTES);
    cudaFuncSetAttribute(attn_tc, cudaFuncAttributeMaxDynamicSharedMemorySize,
                         ASMEM_BYTES);

    __nv_bfloat16 *pXh, *pXl, *pWh, *pWl, *pWOh, *pWOl, *pOh, *pOl;
    cudaGetSymbolAddress((void**)&pXh, g_Xh);
    cudaGetSymbolAddress((void**)&pXl, g_Xl);
    cudaGetSymbolAddress((void**)&pWh, g_Wh);
    cudaGetSymbolAddress((void**)&pWl, g_Wl);
    cudaGetSymbolAddress((void**)&pWOh, g_WOh);
    cudaGetSymbolAddress((void**)&pWOl, g_WOl);
    cudaGetSymbolAddress((void**)&pOh, g_Oh);
    cudaGetSymbolAddress((void**)&pOl, g_Ol);

    // Operand preparation
    const int n4x = (Bsz * Tseq * Dmodel) / 4;
    convert_split<<<n4x / 256, 256>>>(x, pXh, pXl, n4x);
    convert_wT<<<dim3(3 * Dmodel / 32, Dmodel / 32), dim3(32, 8)>>>(
        w_attn, pWh, pWl, Dmodel, 3 * Dmodel);
    convert_wT<<<dim3(Dmodel / 32, Dmodel / 32), dim3(32, 8)>>>(
        w_out, pWOh, pWOl, Dmodel, Dmodel);

    // QKV projection + fused scale/rope/split -> split Q/K/V [B,N,T,H]
    gemm_tc<0><<<dim3(48, 32), 256, GSMEM_BYTES>>>(pXh, pXl, pWh, pWl, nullptr,
                                                   cosT, sinT);

    // Tensor-core causal flash attention -> split O [B,T,D]
    attn_tc<<<dim3(Tseq / 128, NHEAD, Bsz), 256, ASMEM_BYTES>>>();

    // Output projection -> d_out
    gemm_tc<1><<<dim3(16, 32), 256, GSMEM_BYTES>>>(pOh, pOl, pWOh, pWOl, out,
                                                   nullptr, nullptr);
}

// round 9
// speedup vs baseline: 5.5123x; 1.3451x over previous
#include <cuda_runtime.h>
#include <cuda_fp16.h>
#include <cstdint>

// Problem constants
#define Bsz    2
#define Tseq   2048
#define Dmodel 2048
#define NHEAD  16
#define HD     128
#define FR     64

// ---------------------------------------------------------------------------
// Scratch (static __device__ — no allocations allowed)
// Scheme: A-operands split into fp16 (hi, lo) — represents fp32 to ~2^-22;
// B-operands rounded to a single fp16 (error ~2^-11, the accuracy budget).
// ---------------------------------------------------------------------------
__device__ __half g_Xh[(size_t)Bsz * Tseq * Dmodel];
__device__ __half g_Xl[(size_t)Bsz * Tseq * Dmodel];
__device__ __half g_W[(size_t)3 * Dmodel * Dmodel];    // w_attn^T [6144][2048]
__device__ __half g_WO[(size_t)Dmodel * Dmodel];       // w_out^T [2048][2048]
__device__ __half g_Qh[(size_t)Bsz * NHEAD * Tseq * HD];
__device__ __half g_Ql[(size_t)Bsz * NHEAD * Tseq * HD];
__device__ __half g_K16[(size_t)Bsz * NHEAD * Tseq * HD];
__device__ __half g_V16[(size_t)Bsz * NHEAD * Tseq * HD];
__device__ __half g_Oh[(size_t)Bsz * Tseq * Dmodel];
__device__ __half g_Ol[(size_t)Bsz * Tseq * Dmodel];

// ---------------------------------------------------------------------------
// mma.sync / ldmatrix / cp.async helpers (sm_80+ baseline PTX)
// ---------------------------------------------------------------------------
__device__ __forceinline__ uint32_t smem_u32(const void* p) {
    uint32_t a;
    asm("{ .reg .u64 t; cvta.to.shared.u64 t, %1; cvt.u32.u64 %0, t; }"
        : "=r"(a) : "l"(p));
    return a;
}

#define LDSM4(r, addr) \
    asm volatile("ldmatrix.sync.aligned.m8n8.x4.shared.b16 {%0,%1,%2,%3}, [%4];" \
                 : "=r"((r)[0]), "=r"((r)[1]), "=r"((r)[2]), "=r"((r)[3]) \
                 : "r"(addr))
#define LDSM4T(r, addr) \
    asm volatile("ldmatrix.sync.aligned.m8n8.x4.trans.shared.b16 {%0,%1,%2,%3}, [%4];" \
                 : "=r"((r)[0]), "=r"((r)[1]), "=r"((r)[2]), "=r"((r)[3]) \
                 : "r"(addr))

__device__ __forceinline__ void mma_16816(float* c, const uint32_t* a,
                                          const uint32_t* b) {
    asm volatile(
        "mma.sync.aligned.m16n8k16.row.col.f32.f16.f16.f32 "
        "{%0,%1,%2,%3}, {%4,%5,%6,%7}, {%8,%9}, {%0,%1,%2,%3};"
        : "+f"(c[0]), "+f"(c[1]), "+f"(c[2]), "+f"(c[3])
        : "r"(a[0]), "r"(a[1]), "r"(a[2]), "r"(a[3]), "r"(b[0]), "r"(b[1]));
}

#define CP16(dst, src) \
    asm volatile("cp.async.cg.shared.global [%0], [%1], 16;" \
                 :: "r"(dst), "l"(src) : "memory")
#define CP_COMMIT() asm volatile("cp.async.commit_group;" ::: "memory")
#define CP_WAIT1()  asm volatile("cp.async.wait_group 1;" ::: "memory")
#define CP_WAIT0()  asm volatile("cp.async.wait_group 0;" ::: "memory")

__device__ __forceinline__ uint32_t pack_h2(float x, float y) {
    __half2 h = __floats2half2_rn(x, y);
    return *(uint32_t*)&h;
}
__device__ __forceinline__ void split_store_h(__half* hi, __half* lo,
                                              size_t idx, float v0, float v1) {
    const __half h0 = __float2half_rn(v0);
    const __half h1 = __float2half_rn(v1);
    const __half l0 = __float2half_rn(v0 - __half2float(h0));
    const __half l1 = __float2half_rn(v1 - __half2float(h1));
    *(__half2*)&hi[idx] = __halves2half2(h0, h1);
    *(__half2*)&lo[idx] = __halves2half2(l0, l1);
}

// ---------------------------------------------------------------------------
// fp32 -> (fp16 hi, fp16 lo) elementwise split
// ---------------------------------------------------------------------------
__global__ void convert_split(const float* __restrict__ in,
                              __half* __restrict__ hi,
                              __half* __restrict__ lo, int n4) {
    const int i = blockIdx.x * blockDim.x + threadIdx.x;
    if (i >= n4) return;
    float4 a = ((const float4*)in)[i];
    const __half h0 = __float2half_rn(a.x), h1 = __float2half_rn(a.y);
    const __half h2 = __float2half_rn(a.z), h3 = __float2half_rn(a.w);
    ((__half2*)hi)[i * 2 + 0] = __halves2half2(h0, h1);
    ((__half2*)hi)[i * 2 + 1] = __halves2half2(h2, h3);
    ((__half2*)lo)[i * 2 + 0] = __halves2half2(
        __float2half_rn(a.x - __half2float(h0)),
        __float2half_rn(a.y - __half2float(h1)));
    ((__half2*)lo)[i * 2 + 1] = __halves2half2(
        __float2half_rn(a.z - __half2float(h2)),
        __float2half_rn(a.w - __half2float(h3)));
}

// ---------------------------------------------------------------------------
// Transpose W [K, Ncols] (row-major) -> Wt [Ncols, K], single fp16 rounding
// ---------------------------------------------------------------------------
__global__ void convert_wT(const float* __restrict__ W,
                           __half* __restrict__ T, int K, int Ncols) {
    __shared__ float s[32][33];
    const int n0 = blockIdx.x * 32, k0 = blockIdx.y * 32;
    const int tx = threadIdx.x, ty = threadIdx.y;  // (32, 8)
#pragma unroll
    for (int i = 0; i < 4; i++)
        s[ty + i * 8][tx] = W[(size_t)(k0 + ty + i * 8) * Ncols + n0 + tx];
    __syncthreads();
#pragma unroll
    for (int i = 0; i < 4; i++) {
        T[(size_t)(n0 + ty + i * 8) * K + k0 + tx] =
            __float2half_rn(s[tx][ty + i * 8]);
    }
}

// ---------------------------------------------------------------------------
// 2-pass fp16 GEMM: C = (Ah + Al) * B^T, B single fp16 [NC, 2048] K-major.
// CTA 128x128, K-chunk 32, 8 warps, double-buffered cp.async (3 tiles/stage).
//   MODE 0: QKV proj — fused scale(Q)/rope(K,V); Q split-stored, K/V single.
//   MODE 1: out-proj -> d_out (fp32).
// ---------------------------------------------------------------------------
#define RSTRIDE 40
#define TILE_B  (128 * RSTRIDE * 2)     // 10240
#define STAGE_B (3 * TILE_B)            // 30720
#define GSMEM_BYTES (2 * STAGE_B)       // 61440

template <int MODE>
__global__ void __launch_bounds__(256, 2) gemm_tc(
    const __half* __restrict__ Ah, const __half* __restrict__ Al,
    const __half* __restrict__ B, float* __restrict__ C,
    const float* __restrict__ cosT, const float* __restrict__ sinT) {
    extern __shared__ char smem[];
    const uint32_t sb = smem_u32(smem);

    const int tid = threadIdx.x;
    const int lane = tid & 31, warp = tid >> 5;
    const int m0 = blockIdx.y * 128, c0 = blockIdx.x * 128;
    const int wm = (warp & 1) * 64, wn = (warp >> 1) * 32;

    const int a_row = wm + (lane & 15);
    const int a_colb = (lane >> 4) * 16;
    const int b_row = wn + (lane & 7) + ((lane >> 4) << 3);
    const int b_colb = ((lane >> 3) & 1) * 16;

    const __half* Ah0 = Ah + (size_t)m0 * 2048;
    const __half* Al0 = Al + (size_t)m0 * 2048;
    const __half* B0 = B + (size_t)c0 * 2048;

    float acc[4][4][4];
#pragma unroll
    for (int i = 0; i < 4; i++)
#pragma unroll
        for (int j = 0; j < 4; j++)
#pragma unroll
            for (int r = 0; r < 4; r++) acc[i][j][r] = 0.f;

    auto load_stage = [&](int stage, int kc) {
        const uint32_t s0 = sb + stage * STAGE_B;
        const size_t ko = (size_t)kc * 32;
#pragma unroll
        for (int h = 0; h < 2; h++) {
            const int cch = tid + h * 256;          // 0..511
            const int row = cch >> 2, q = cch & 3;
            const uint32_t so = (uint32_t)row * (RSTRIDE * 2) + q * 16;
            const size_t go = (size_t)row * 2048 + ko + q * 8;
            CP16(s0 + 0 * TILE_B + so, Ah0 + go);
            CP16(s0 + 1 * TILE_B + so, Al0 + go);
            CP16(s0 + 2 * TILE_B + so, B0 + go);
        }
        CP_COMMIT();
    };

    load_stage(0, 0);

    for (int c = 0; c < 64; c++) {
        if (c < 63) {
            load_stage((c + 1) & 1, c + 1);
            CP_WAIT1();
        } else {
            CP_WAIT0();
        }
        __syncthreads();

        const uint32_t st = sb + (c & 1) * STAGE_B;
        const uint32_t tAh = st + 0 * TILE_B, tAl = st + 1 * TILE_B;
        const uint32_t tB = st + 2 * TILE_B;

#pragma unroll
        for (int t = 0; t < 2; t++) {
            const int tcb = t * 32;
            uint32_t aF[4][4], bF[4][2];

            // load aH + b, pass 1: Ah * B
#pragma unroll
            for (int mf = 0; mf < 4; mf++)
                LDSM4(aF[mf], tAh + (a_row + mf * 16) * (RSTRIDE * 2) + tcb + a_colb);
#pragma unroll
            for (int nf2 = 0; nf2 < 2; nf2++) {
                uint32_t r[4];
                LDSM4(r, tB + (b_row + nf2 * 16) * (RSTRIDE * 2) + tcb + b_colb);
                bF[nf2 * 2][0] = r[0]; bF[nf2 * 2][1] = r[1];
                bF[nf2 * 2 + 1][0] = r[2]; bF[nf2 * 2 + 1][1] = r[3];
            }
#pragma unroll
            for (int mf = 0; mf < 4; mf++)
#pragma unroll
                for (int nf = 0; nf < 4; nf++) mma_16816(acc[mf][nf], aF[mf], bF[nf]);

            // load aL (reuses aF), pass 2: Al * B
#pragma unroll
            for (int mf = 0; mf < 4; mf++)
                LDSM4(aF[mf], tAl + (a_row + mf * 16) * (RSTRIDE * 2) + tcb + a_colb);
#pragma unroll
            for (int mf = 0; mf < 4; mf++)
#pragma unroll
                for (int nf = 0; nf < 4; nf++) mma_16816(acc[mf][nf], aF[mf], bF[nf]);
        }
        __syncthreads();
    }

    // Epilogue
    const int g = lane >> 2, tg = lane & 3;
#pragma unroll
    for (int mf = 0; mf < 4; mf++) {
#pragma unroll
        for (int nf = 0; nf < 4; nf++) {
            const int row0 = m0 + wm + mf * 16 + g;
            const int col = c0 + wn + nf * 8 + tg * 2;  // even
            if (MODE == 0) {
                const int part = col >> 11;           // 0=Q,1=K,2=V
                const int nh = (col >> 7) & 15;
                const int h = col & 127;              // even
                const int f = h >> 1;
#pragma unroll
                for (int rr = 0; rr < 2; rr++) {
                    const int row = row0 + rr * 8;
                    const int bb = row >> 11, tt = row & 2047;
                    float v0 = acc[mf][nf][rr * 2], v1 = acc[mf][nf][rr * 2 + 1];
                    const size_t idx =
                        ((size_t)((bb << 4) + nh) * Tseq + tt) * HD + h;
                    if (part == 0) {
                        v0 *= 0.08838834764831845f;   // 1/sqrt(128)
                        v1 *= 0.08838834764831845f;
                        split_store_h(g_Qh, g_Ql, idx, v0, v1);
                    } else {
                        const float cs = cosT[tt * FR + f];
                        const float sn = sinT[tt * FR + f];
                        const float r_ = v0 * cs - v1 * sn;
                        const float i_ = v0 * sn + v1 * cs;
                        __half* dst = (part == 1) ? g_K16 : g_V16;
                        *(__half2*)&dst[idx] = __floats2half2_rn(r_, i_);
                    }
                }
            } else {
#pragma unroll
                for (int rr = 0; rr < 2; rr++) {
                    const int row = row0 + rr * 8;
                    float2* dp = (float2*)&C[(size_t)row * 2048 + col];
                    *dp = make_float2(acc[mf][nf][rr * 2], acc[mf][nf][rr * 2 + 1]);
                }
            }
        }
    }
}

// ---------------------------------------------------------------------------
// Tensor-core flash attention (causal), 2-pass fp16.
// QK: (Qh + Ql) * K16.  PV: (Ph + Pl) * V16.  K/V single-buffer per stage.
// ---------------------------------------------------------------------------
#define AT_RS   136
#define AT_RSB  (AT_RS * 2)
#define QT_B    (128 * AT_RSB)              // 34816
#define KVT_B   (64 * AT_RSB)               // 17408
#define ASMEM_BYTES (2 * QT_B + 4 * KVT_B)  // 139264

__global__ void __launch_bounds__(256) attn_tc() {
    extern __shared__ char smem[];
    const uint32_t sb = smem_u32(smem);
    const int b = blockIdx.z, n = blockIdx.y, qt = blockIdx.x;
    const int tid = threadIdx.x;
    const int lane = tid & 31, warp = tid >> 5;
    const int g = lane >> 2, t4 = lane & 3;

    const size_t headoff = (size_t)(b * NHEAD + n) * Tseq * HD;
    const __half* Qhg = g_Qh + headoff + (size_t)qt * 128 * HD;
    const __half* Qlg = g_Ql + headoff + (size_t)qt * 128 * HD;

    for (int i = tid; i < 2048; i += 256) {
        const int row = i >> 4, q = i & 15;
        const uint32_t so = (uint32_t)row * AT_RSB + q * 16;
        const size_t go = (size_t)row * HD + q * 8;
        CP16(sb + so, Qhg + go);
        CP16(sb + QT_B + so, Qlg + go);
    }
    CP_COMMIT();

    auto load_kv = [&](int stage, int kt) {
        const uint32_t base = sb + 2 * QT_B + stage * (2 * KVT_B);
        const size_t koff = headoff + (size_t)kt * 64 * HD;
        const __half* Kp = g_K16 + koff;
        const __half* Vp = g_V16 + koff;
        for (int i = tid; i < 1024; i += 256) {
            const int row = i >> 4, q = i & 15;
            const uint32_t so = (uint32_t)row * AT_RSB + q * 16;
            const size_t go = (size_t)row * HD + q * 8;
            CP16(base + 0 * KVT_B + so, Kp + go);
            CP16(base + 1 * KVT_B + so, Vp + go);
        }
        CP_COMMIT();
    };

    load_kv(0, 0);
    const int ntiles = 2 * qt + 2;

    float o[16][4];
#pragma unroll
    for (int f = 0; f < 16; f++)
#pragma unroll
        for (int r = 0; r < 4; r++) o[f][r] = 0.f;
    float m0r = -1e30f, m1r = -1e30f, l0 = 0.f, l1 = 0.f;

    const int qrow0 = qt * 128 + warp * 16;
    const uint32_t qa = sb + (uint32_t)(warp * 16 + (lane & 15)) * AT_RSB +
                        (lane >> 4) * 16;
    const int kb_row = (lane & 7) + ((lane >> 4) << 3);
    const int kb_colb = ((lane >> 3) & 1) * 16;
    const int v_row = lane & 15;
    const int v_colb = (lane >> 4) * 16;

    for (int kt = 0; kt < ntiles; kt++) {
        if (kt + 1 < ntiles) {
            load_kv((kt + 1) & 1, kt + 1);
            CP_WAIT1();
        } else {
            CP_WAIT0();
        }
        __syncthreads();

        const uint32_t base = sb + 2 * QT_B + (kt & 1) * (2 * KVT_B);
        const uint32_t tK = base, tV = base + KVT_B;

        // ---- S = (Qh + Ql) K^T ----
        float s[8][4];
#pragma unroll
        for (int nf = 0; nf < 8; nf++)
#pragma unroll
            for (int r = 0; r < 4; r++) s[nf][r] = 0.f;

#pragma unroll
        for (int ks = 0; ks < 8; ks++) {
            uint32_t aH[4], aL[4];
            LDSM4(aH, qa + ks * 32);
            LDSM4(aL, qa + QT_B + ks * 32);
            uint32_t rK[2][4];
            {
                const uint32_t ko0 = (uint32_t)(kb_row)*AT_RSB + ks * 32 + kb_colb;
                LDSM4(rK[0], tK + ko0);
            }
#pragma unroll
            for (int kn = 0; kn < 4; kn++) {
                const int cur = kn & 1;
                if (kn < 3) {
                    const uint32_t ko =
                        (uint32_t)((kn + 1) * 16 + kb_row) * AT_RSB + ks * 32 + kb_colb;
                    LDSM4(rK[cur ^ 1], tK + ko);
                }
                mma_16816(s[2 * kn], aH, rK[cur]);
                mma_16816(s[2 * kn + 1], aH, rK[cur] + 2);
                mma_16816(s[2 * kn], aL, rK[cur]);
                mma_16816(s[2 * kn + 1], aL, rK[cur] + 2);
            }
        }

        if (kt * 64 + 63 > qrow0) {
            const int r0 = qrow0 + g, r1 = r0 + 8;
#pragma unroll
            for (int nf = 0; nf < 8; nf++) {
                const int k0 = kt * 64 + nf * 8 + 2 * t4;
                if (k0 > r0) s[nf][0] = -1e30f;
                if (k0 + 1 > r0) s[nf][1] = -1e30f;
                if (k0 > r1) s[nf][2] = -1e30f;
                if (k0 + 1 > r1) s[nf][3] = -1e30f;
            }
        }

        float tm0 = -1e30f, tm1 = -1e30f;
#pragma unroll
        for (int nf = 0; nf < 8; nf++) {
            tm0 = fmaxf(tm0, fmaxf(s[nf][0], s[nf][1]));
            tm1 = fmaxf(tm1, fmaxf(s[nf][2], s[nf][3]));
        }
        tm0 = fmaxf(tm0, __shfl_xor_sync(0xffffffffu, tm0, 1));
        tm0 = fmaxf(tm0, __shfl_xor_sync(0xffffffffu, tm0, 2));
        tm1 = fmaxf(tm1, __shfl_xor_sync(0xffffffffu, tm1, 1));
        tm1 = fmaxf(tm1, __shfl_xor_sync(0xffffffffu, tm1, 2));
        const float nm0 = fmaxf(m0r, tm0), nm1 = fmaxf(m1r, tm1);
        const float cr0 = __expf(m0r - nm0), cr1 = __expf(m1r - nm1);
        m0r = nm0; m1r = nm1;
        float ps0 = 0.f, ps1 = 0.f;
#pragma unroll
        for (int nf = 0; nf < 8; nf++) {
            s[nf][0] = __expf(s[nf][0] - m0r);
            s[nf][1] = __expf(s[nf][1] - m0r);
            s[nf][2] = __expf(s[nf][2] - m1r);
            s[nf][3] = __expf(s[nf][3] - m1r);
            ps0 += s[nf][0] + s[nf][1];
            ps1 += s[nf][2] + s[nf][3];
        }
        ps0 += __shfl_xor_sync(0xffffffffu, ps0, 1);
        ps0 += __shfl_xor_sync(0xffffffffu, ps0, 2);
        ps1 += __shfl_xor_sync(0xffffffffu, ps1, 1);
        ps1 += __shfl_xor_sync(0xffffffffu, ps1, 2);
        l0 = l0 * cr0 + ps0;
        l1 = l1 * cr1 + ps1;
#pragma unroll
        for (int f = 0; f < 16; f++) {
            o[f][0] *= cr0; o[f][1] *= cr0;
            o[f][2] *= cr1; o[f][3] *= cr1;
        }

        // ---- O += (Ph + Pl) V ----
#pragma unroll
        for (int j = 0; j < 4; j++) {
            uint32_t aPh[4], aPl[4];
#pragma unroll
            for (int hh = 0; hh < 2; hh++) {
                const float* sp = s[2 * j + hh];
#pragma unroll
                for (int rr = 0; rr < 2; rr++) {
                    const float x = sp[rr * 2], y = sp[rr * 2 + 1];
                    const uint32_t hp = pack_h2(x, y);
                    aPh[hh * 2 + rr] = hp;
                    const __half2 hb = *(const __half2*)&hp;
                    aPl[hh * 2 + rr] = pack_h2(x - __half2float(hb.x),
                                               y - __half2float(hb.y));
                }
            }
            uint32_t vK[2][4];
            {
                const uint32_t vo0 = (uint32_t)(j * 16 + v_row) * AT_RSB + v_colb;
                LDSM4T(vK[0], tV + vo0);
            }
#pragma unroll
            for (int dn = 0; dn < 8; dn++) {
                const int cur = dn & 1;
                if (dn < 7) {
                    const uint32_t vo = (uint32_t)(j * 16 + v_row) * AT_RSB +
                                        (dn + 1) * 32 + v_colb;
                    LDSM4T(vK[cur ^ 1], tV + vo);
                }
                mma_16816(o[2 * dn], aPh, vK[cur]);
                mma_16816(o[2 * dn + 1], aPh, vK[cur] + 2);
                mma_16816(o[2 * dn], aPl, vK[cur]);
                mma_16816(o[2 * dn + 1], aPl, vK[cur] + 2);
            }
        }
        __syncthreads();
    }

    const float inv0 = 1.f / l0, inv1 = 1.f / l1;
    const int r0 = qrow0 + g, r1 = r0 + 8;
#pragma unroll
    for (int f = 0; f < 16; f++) {
        const int col = n * HD + f * 8 + t4 * 2;
        const size_t i0 = ((size_t)(b * Tseq + r0)) * Dmodel + col;
        const size_t i1 = ((size_t)(b * Tseq + r1)) * Dmodel + col;
        split_store_h(g_Oh, g_Ol, i0, o[f][0] * inv0, o[f][1] * inv0);
        split_store_h(g_Oh, g_Ol, i1, o[f][2] * inv1, o[f][3] * inv1);
    }
}

// ---------------------------------------------------------------------------
// Host launcher (graph-capturable: kernel launches only)
// Inputs: 0=x, 1=mask(unused: exact causal tril), 2=cos, 3=sin, 4=w_attn, 5=w_out
// ---------------------------------------------------------------------------
extern "C" void kernel_launch(void* const* d_in, const int* in_sizes, int n_in,
                              void* d_out, int out_size) {
    const float* x = (const float*)d_in[0];
    const float* cosT = (const float*)d_in[2];
    const float* sinT = (const float*)d_in[3];
    const float* w_attn = (const float*)d_in[4];
    const float* w_out = (const float*)d_in[5];
    float* out = (float*)d_out;

    cudaFuncSetAttribute(gemm_tc<0>, cudaFuncAttributeMaxDynamicSharedMemorySize,
                         GSMEM_BYTES);
    cudaFuncSetAttribute(gemm_tc<1>, cudaFuncAttributeMaxDynamicSharedMemorySize,
                         GSMEM_BYTES);
    cudaFuncSetAttribute(attn_tc, cudaFuncAttributeMaxDynamicSharedMemorySize,
                         ASMEM_BYTES);

    __half *pXh, *pXl, *pW, *pWO, *pOh, *pOl;
    cudaGetSymbolAddress((void**)&pXh, g_Xh);
    cudaGetSymbolAddress((void**)&pXl, g_Xl);
    cudaGetSymbolAddress((void**)&pW, g_W);
    cudaGetSymbolAddress((void**)&pWO, g_WO);
    cudaGetSymbolAddress((void**)&pOh, g_Oh);
    cudaGetSymbolAddress((void**)&pOl, g_Ol);

    // Operand preparation
    const int n4x = (Bsz * Tseq * Dmodel) / 4;
    convert_split<<<n4x / 256, 256>>>(x, pXh, pXl, n4x);
    convert_wT<<<dim3(3 * Dmodel / 32, Dmodel / 32), dim3(32, 8)>>>(
        w_attn, pW, Dmodel, 3 * Dmodel);
    convert_wT<<<dim3(Dmodel / 32, Dmodel / 32), dim3(32, 8)>>>(
        w_out, pWO, Dmodel, Dmodel);

    // QKV projection + fused scale/rope -> Q (split) / K,V (single) [B,N,T,H]
    gemm_tc<0><<<dim3(48, 32), 256, GSMEM_BYTES>>>(pXh, pXl, pW, nullptr,
                                                   cosT, sinT);

    // Tensor-core causal flash attention -> split O [B,T,D]
    attn_tc<<<dim3(Tseq / 128, NHEAD, Bsz), 256, ASMEM_BYTES>>>();

    // Output projection -> d_out
    gemm_tc<1><<<dim3(16, 32), 256, GSMEM_BYTES>>>(pOh, pOl, pWO, out,
                                                   nullptr, nullptr);
}